// round 12
// baseline (speedup 1.0000x reference)
#include <cuda_runtime.h>
#include <math.h>
#include <stdint.h>

#define S_  40
#define B_  32
#define T_  60
#define H_  256
#define F_  64
#define DIN 320
#define OUTD 128
#define GH  1024   // 4*H
#define CLUSTER 8

typedef unsigned long long ull;

// ---------------- device scratch ----------------
__device__ float g_sen[B_ * S_ * DIN];          // sen[b][s][0:320]
__device__ float g_XW[2][B_ * S_ * GH];         // [dir][b*S+s][1024]
__device__ float g_hfinal[2][B_][H_];
__device__ int g_mask_u8;

// ---------------- f32x2 helpers ----------------
__device__ __forceinline__ ull packf2(float a, float b) {
    ull r; asm("mov.b64 %0, {%1,%2};" : "=l"(r) : "f"(a), "f"(b)); return r;
}
__device__ __forceinline__ ull fma2(ull a, ull b, ull c) {
    ull d; asm("fma.rn.f32x2 %0, %1, %2, %3;" : "=l"(d) : "l"(a), "l"(b), "l"(c)); return d;
}
__device__ __forceinline__ ull addf2(ull a, ull b) {
    ull d; asm("add.rn.f32x2 %0, %1, %2;" : "=l"(d) : "l"(a), "l"(b)); return d;
}
__device__ __forceinline__ void unpackf2(ull v, float& lo, float& hi) {
    asm("mov.b64 {%0,%1}, %2;" : "=f"(lo), "=f"(hi) : "l"(v));
}
__device__ __forceinline__ uint32_t smem_u32(const void* p) {
    uint32_t a;
    asm("{ .reg .u64 t; cvta.to.shared.u64 t, %1; cvt.u32.u64 %0, t; }" : "=r"(a) : "l"(p));
    return a;
}
__device__ __forceinline__ uint32_t mapa_u32(uint32_t saddr, int rank) {
    uint32_t r;
    asm("mapa.shared::cluster.u32 %0, %1, %2;" : "=r"(r) : "r"(saddr), "r"(rank));
    return r;
}
__device__ __forceinline__ void st_async_v4(uint32_t daddr, float a, float b, float c, float d,
                                            uint32_t mbar) {
    asm volatile(
        "st.async.weak.shared::cluster.mbarrier::complete_tx::bytes.v4.f32 "
        "[%0], {%1,%2,%3,%4}, [%5];"
        :: "r"(daddr), "f"(a), "f"(b), "f"(c), "f"(d), "r"(mbar) : "memory");
}
__device__ __forceinline__ void mbar_init(uint32_t mbar, uint32_t cnt) {
    asm volatile("mbarrier.init.shared.b64 [%0], %1;" :: "r"(mbar), "r"(cnt) : "memory");
}
__device__ __forceinline__ void mbar_expect_tx(uint32_t mbar, uint32_t bytes) {
    asm volatile("mbarrier.arrive.expect_tx.shared.b64 _, [%0], %1;"
                 :: "r"(mbar), "r"(bytes) : "memory");
}
__device__ __forceinline__ void mbar_wait(uint32_t mbar, uint32_t parity) {
    asm volatile(
        "{\n\t.reg .pred P;\n\t"
        "WAIT_%=:\n\t"
        "mbarrier.try_wait.parity.acquire.cluster.shared::cta.b64 P, [%0], %1;\n\t"
        "@!P bra WAIT_%=;\n\t}"
        :: "r"(mbar), "r"(parity) : "memory");
}
#define CLUSTER_ARRIVE() asm volatile("barrier.cluster.arrive.aligned;" ::: "memory")
#define CLUSTER_WAIT()   asm volatile("barrier.cluster.wait.aligned;"   ::: "memory")
#define CLUSTER_SYNC() do { CLUSTER_ARRIVE(); CLUSTER_WAIT(); } while (0)

__device__ __forceinline__ float htanh(float x) {
    float y; asm("tanh.approx.f32 %0, %1;" : "=f"(y) : "f"(x)); return y;
}
__device__ __forceinline__ float hsig(float x) {
    return 0.5f * htanh(0.5f * x) + 0.5f;
}
__device__ __forceinline__ uint32_t to_tf32(float f) {
    uint32_t u; asm("cvt.rna.tf32.f32 %0, %1;" : "=r"(u) : "f"(f)); return u;
}

// ---------------- mask dtype detection ----------------
__global__ void detect_mask_kernel(const uint4* __restrict__ m, int nwords4) {
    __shared__ int found;
    if (threadIdx.x == 0) found = 0;
    __syncthreads();
    for (int i = threadIdx.x; i < nwords4; i += blockDim.x) {
        uint4 v = m[i];
        if ((v.x | v.y | v.z | v.w) & 0xFFFFFF00u) { found = 1; break; }
    }
    __syncthreads();
    if (threadIdx.x == 0) g_mask_u8 = found;
}

// ---------------- stage 1: gather + attention pooling + feature sum ----
__global__ void stage1_kernel(const int* __restrict__ x,
                              const unsigned char* __restrict__ xmask,
                              const float* __restrict__ xfeat,
                              const float* __restrict__ emb,
                              const float* __restrict__ attn_w,
                              const float* __restrict__ attn_b) {
    extern __shared__ float sm[];
    float* e_s     = sm;
    float* score_s = sm + T_ * H_;
    float* alpha_s = score_s + 64;

    int bs = blockIdx.x;
    int b = bs / S_, s = bs % S_;
    int tid = threadIdx.x, warp = tid >> 5, lane = tid & 31;
    int u8 = g_mask_u8;
    long base = (long)(b * S_ + s) * T_;
    float ab = attn_b[0];

    for (int t = warp; t < T_; t += 8) {
        int xi = x[base + t];
        long mi = base + t;
        unsigned char mv = u8 ? xmask[mi] : xmask[mi * 4];
        int valid = (mv == 0);
        float4 v0, v1;
        if (valid) {
            const float4* er = (const float4*)(emb + (long)xi * H_);
            v0 = er[lane]; v1 = er[lane + 32];
        } else {
            v0 = make_float4(0.f, 0.f, 0.f, 0.f); v1 = v0;
        }
        float4* ed = (float4*)(e_s + t * H_);
        ed[lane] = v0; ed[lane + 32] = v1;
        const float4* aw = (const float4*)attn_w;
        float4 w0 = aw[lane], w1 = aw[lane + 32];
        float p = v0.x*w0.x + v0.y*w0.y + v0.z*w0.z + v0.w*w0.w
                + v1.x*w1.x + v1.y*w1.y + v1.z*w1.z + v1.w*w1.w;
        #pragma unroll
        for (int o = 16; o; o >>= 1) p += __shfl_xor_sync(0xffffffffu, p, o);
        if (lane == 0) score_s[t] = valid ? (p + ab) : -1e30f;
    }
    __syncthreads();

    if (warp == 0) {
        float s0 = (lane < T_)      ? score_s[lane]      : -1e30f;
        float s1 = (lane + 32 < T_) ? score_s[lane + 32] : -1e30f;
        float mx = fmaxf(s0, s1);
        #pragma unroll
        for (int o = 16; o; o >>= 1) mx = fmaxf(mx, __shfl_xor_sync(0xffffffffu, mx, o));
        float e0 = (s0 > -1e29f) ? expf(s0 - mx) : 0.f;
        float e1 = (s1 > -1e29f) ? expf(s1 - mx) : 0.f;
        float sum = e0 + e1;
        #pragma unroll
        for (int o = 16; o; o >>= 1) sum += __shfl_xor_sync(0xffffffffu, sum, o);
        float inv = (mx > -1e29f) ? (1.f / sum) : 0.f;
        if (lane < T_)      alpha_s[lane]      = e0 * inv;
        if (lane + 32 < T_) alpha_s[lane + 32] = e1 * inv;
    }
    __syncthreads();

    float acc = 0.f;
    #pragma unroll 4
    for (int t = 0; t < T_; t++) acc += alpha_s[t] * e_s[t * H_ + tid];
    g_sen[(b * S_ + s) * DIN + tid] = acc;

    if (tid < F_) {
        float fa = 0.f;
        const float* fp = xfeat + base * F_ + tid;
        #pragma unroll 4
        for (int t = 0; t < T_; t++)
            if (score_s[t] > -1e29f) fa += fp[t * F_];
        g_sen[(b * S_ + s) * DIN + H_ + tid] = fa;
    }
}

// ---------------- XW GEMM via tf32 tensor cores, 64-row tiles + lens skip ---
#define PA 36
#define PW 36
__global__ void __launch_bounds__(256) xw_gemm_kernel(
    const float* __restrict__ wf, const float* __restrict__ wb,
    const float* __restrict__ bih_f, const float* __restrict__ bhh_f,
    const float* __restrict__ bih_b, const float* __restrict__ bhh_b,
    const int* __restrict__ lens) {
    int m0 = blockIdx.x * 64;
    {
        bool live = false;
        int b0 = m0 / S_, b1 = (m0 + 63) / S_;
        for (int b = b0; b <= b1 && b < B_; b++) {
            int glen = lens[(b >> 2) << 2];          // group max (sorted desc)
            int row_lo = b * S_;
            int s_start = (m0 > row_lo) ? (m0 - row_lo) : 0;
            if (row_lo < m0 + 64 && s_start < glen) { live = true; break; }
        }
        if (!live) return;
    }
    __shared__ uint32_t As[64 * PA];
    __shared__ uint32_t Ws[128 * PW];
    int dir = blockIdx.z;
    const float* W  = dir ? wb : wf;
    const float* b1p = dir ? bih_b : bih_f;
    const float* b2p = dir ? bhh_b : bhh_f;
    int n0 = blockIdx.y * 128;
    int tid = threadIdx.x, lane = tid & 31, warp = tid >> 5;
    int wm = warp & 1, wn = warp >> 1;
    int g = lane >> 2, tq = lane & 3;

    float acc[2][4][4];
    #pragma unroll
    for (int mi = 0; mi < 2; mi++)
        #pragma unroll
        for (int ni = 0; ni < 4; ni++)
            #pragma unroll
            for (int c = 0; c < 4; c++) acc[mi][ni][c] = 0.f;

    for (int kt = 0; kt < DIN; kt += 32) {
        #pragma unroll
        for (int l = 0; l < 2; l++) {
            int i = tid + l * 256;
            int r = i >> 3, c4 = (i & 7) * 4;
            float4 v = *(const float4*)(g_sen + (long)(m0 + r) * DIN + kt + c4);
            uint32_t* d = As + r * PA + c4;
            d[0] = to_tf32(v.x); d[1] = to_tf32(v.y);
            d[2] = to_tf32(v.z); d[3] = to_tf32(v.w);
        }
        #pragma unroll
        for (int l = 0; l < 4; l++) {
            int i = tid + l * 256;
            int r = i >> 3, c4 = (i & 7) * 4;
            float4 v = *(const float4*)(W + (long)(n0 + r) * DIN + kt + c4);
            uint32_t* d = Ws + r * PW + c4;
            d[0] = to_tf32(v.x); d[1] = to_tf32(v.y);
            d[2] = to_tf32(v.z); d[3] = to_tf32(v.w);
        }
        __syncthreads();

        #pragma unroll
        for (int ks = 0; ks < 4; ks++) {
            int kb = ks * 8;
            uint32_t a[2][4];
            #pragma unroll
            for (int mi = 0; mi < 2; mi++) {
                int row = wm * 32 + mi * 16 + g;
                a[mi][0] = As[row * PA + kb + tq];
                a[mi][1] = As[(row + 8) * PA + kb + tq];
                a[mi][2] = As[row * PA + kb + tq + 4];
                a[mi][3] = As[(row + 8) * PA + kb + tq + 4];
            }
            uint32_t bfr[4][2];
            #pragma unroll
            for (int ni = 0; ni < 4; ni++) {
                int col = wn * 32 + ni * 8 + g;
                bfr[ni][0] = Ws[col * PW + kb + tq];
                bfr[ni][1] = Ws[col * PW + kb + tq + 4];
            }
            #pragma unroll
            for (int mi = 0; mi < 2; mi++)
                #pragma unroll
                for (int ni = 0; ni < 4; ni++) {
                    float* c = acc[mi][ni];
                    asm("mma.sync.aligned.m16n8k8.row.col.f32.tf32.tf32.f32 "
                        "{%0,%1,%2,%3}, {%4,%5,%6,%7}, {%8,%9}, {%0,%1,%2,%3};"
                        : "+f"(c[0]), "+f"(c[1]), "+f"(c[2]), "+f"(c[3])
                        : "r"(a[mi][0]), "r"(a[mi][1]), "r"(a[mi][2]), "r"(a[mi][3]),
                          "r"(bfr[ni][0]), "r"(bfr[ni][1]));
                }
        }
        __syncthreads();
    }

    float* C = g_XW[dir];
    #pragma unroll
    for (int ni = 0; ni < 4; ni++) {
        int col = n0 + wn * 32 + ni * 8 + 2 * tq;
        float bb0 = b1p[col] + b2p[col];
        float bb1 = b1p[col + 1] + b2p[col + 1];
        #pragma unroll
        for (int mi = 0; mi < 2; mi++) {
            int row = m0 + wm * 32 + mi * 16 + g;
            *(float2*)(C + (long)row * GH + col) =
                make_float2(acc[mi][ni][0] + bb0, acc[mi][ni][1] + bb1);
            *(float2*)(C + (long)(row + 8) * GH + col) =
                make_float2(acc[mi][ni][2] + bb0, acc[mi][ni][3] + bb1);
        }
    }
}

// ---------------- clustered bidirectional LSTM ----------------
// R11 structure + (a) XW prefetch warp-specialized to warps 8-11 via
// double-buffered xw_s smem (epilogue warps issue NO LDGs), (b) g_hfinal
// written once post-loop from the final h buffer.
__global__ void __launch_bounds__(512, 1) __cluster_dims__(CLUSTER, 1, 1)
lstm_kernel(const float* __restrict__ whh_f, const float* __restrict__ whh_b,
            const int* __restrict__ lens) {
    __shared__ __align__(16) float h_s[2 * 1024];     // [p][b:4][k:256]
    __shared__ __align__(16) float g_part[4 * 512];   // [wks][gr:128][b:4]
    __shared__ __align__(16) float xw_s[2][512];      // [buf][g:4][j:128]
    __shared__ __align__(8)  ull  mbar[2];

    int dir = blockIdx.x >> 6;
    int bg  = (blockIdx.x >> 3) & 7;
    int rank; asm("mov.u32 %0, %%cluster_ctarank;" : "=r"(rank));
    int tid = threadIdx.x, lane = tid & 31, warp = tid >> 5;
    int wks = warp & 3, gate = warp >> 2;
    int kk = lane >> 4, lr = lane & 15;
    const float* whh = dir ? whh_b : whh_f;

    int gu0 = 32 * rank + 2 * lr;
    int kbase = 64 * wks + 32 * kk;
    ull wp0[16], wp1[16];
    {
        const ulonglong2* w0p = (const ulonglong2*)(whh + (long)(gate * H_ + gu0) * H_ + kbase);
        const ulonglong2* w1p = (const ulonglong2*)(whh + (long)(gate * H_ + gu0 + 1) * H_ + kbase);
        #pragma unroll
        for (int q = 0; q < 8; q++) {
            ulonglong2 v0 = w0p[q], v1 = w1p[q];
            wp0[2*q] = v0.x; wp0[2*q+1] = v0.y;
            wp1[2*q] = v1.x; wp1[2*q+1] = v1.y;
        }
    }
    for (int i = tid; i < 2048; i += 512) h_s[i] = 0.f;

    uint32_t hs_base = smem_u32(h_s);
    uint32_t mb0 = smem_u32(&mbar[0]);
    uint32_t mbd0 = mb0 - hs_base;
    uint32_t mbd1 = smem_u32(&mbar[1]) - hs_base;
    if (tid == 0) { mbar_init(mb0, 1); mbar_init(mb0 + (mbd1 - mbd0), 1); }

    int e_u = tid >> 2, e_b = tid & 3;           // epilogue identity (tid<128)
    int e_gu = 32 * rank + e_u;
    int e_len = lens[bg * 4 + e_b];
    int len_grp = lens[bg * 4];                  // group max (lens sorted descending)
    float c_reg = 0.f;
    const float* XWd = g_XW[dir];

    // prefetcher identity (warps 8-11, j = tid-256 in [0,128))
    int pf_j = tid - 256;
    bool pf = (pf_j >= 0 && pf_j < 128);
    long pf_row = (long)(bg * 4 + (pf_j & 3)) * S_;
    int  pf_col = 32 * rank + (pf_j >> 2);

    uint32_t peer_base[CLUSTER];
    #pragma unroll
    for (int prr = 0; prr < CLUSTER; prr++) peer_base[prr] = mapa_u32(hs_base, prr);
    int rot = (tid >> 2) & 7;

    int t0    = dir ? (S_ - len_grp) : 0;
    int t_end = dir ? S_ : len_grp;

    // preload XW for first step into xw_s[t0&1]
    if (pf) {
        int s0 = dir ? (len_grp - 1) : 0;
        long xb = (pf_row + s0) * GH + pf_col;
        #pragma unroll
        for (int g = 0; g < 4; g++) xw_s[t0 & 1][g * 128 + pf_j] = XWd[xb + g * H_];
    }
    __syncthreads();        // drain xw_s / h_s init
    CLUSTER_SYNC();         // zero-init h + mbar init visible cluster-wide

    uint32_t ph0 = 0, ph1 = 0;

    for (int t = t0; t < t_end; t++) {
        int s = dir ? (S_ - 1 - t) : t;
        int p = t & 1;
        int q = p ^ 1;
        uint32_t mbdq = q ? mbd1 : mbd0;
        if (tid == 0) mbar_expect_tx(hs_base + mbdq, 4096);
        const float* hb = h_s + p * 1024 + kbase;

        ull a00=0, a01=0, a02=0, a03=0;
        ull a10=0, a11=0, a12=0, a13=0;
        #pragma unroll
        for (int i = 0; i < 8; i++) {
            ulonglong2 h0 = *(const ulonglong2*)(hb + 4*i);
            ulonglong2 h1 = *(const ulonglong2*)(hb + 256 + 4*i);
            ulonglong2 h2 = *(const ulonglong2*)(hb + 512 + 4*i);
            ulonglong2 h3 = *(const ulonglong2*)(hb + 768 + 4*i);
            ull wa = wp0[2*i], wb = wp0[2*i+1];
            ull wc = wp1[2*i], wd = wp1[2*i+1];
            a00 = fma2(wa, h0.x, a00); a00 = fma2(wb, h0.y, a00);
            a01 = fma2(wa, h1.x, a01); a01 = fma2(wb, h1.y, a01);
            a02 = fma2(wa, h2.x, a02); a02 = fma2(wb, h2.y, a02);
            a03 = fma2(wa, h3.x, a03); a03 = fma2(wb, h3.y, a03);
            a10 = fma2(wc, h0.x, a10); a10 = fma2(wd, h0.y, a10);
            a11 = fma2(wc, h1.x, a11); a11 = fma2(wd, h1.y, a11);
            a12 = fma2(wc, h2.x, a12); a12 = fma2(wd, h2.y, a12);
            a13 = fma2(wc, h3.x, a13); a13 = fma2(wd, h3.y, a13);
        }
        float l0, l1, s00, s01, s02, s03, s10, s11, s12, s13;
        unpackf2(a00, l0, l1); s00 = l0 + l1;
        unpackf2(a01, l0, l1); s01 = l0 + l1;
        unpackf2(a02, l0, l1); s02 = l0 + l1;
        unpackf2(a03, l0, l1); s03 = l0 + l1;
        unpackf2(a10, l0, l1); s10 = l0 + l1;
        unpackf2(a11, l0, l1); s11 = l0 + l1;
        unpackf2(a12, l0, l1); s12 = l0 + l1;
        unpackf2(a13, l0, l1); s13 = l0 + l1;
        ull r00 = packf2(s00, s01), r01 = packf2(s02, s03);
        ull r10 = packf2(s10, s11), r11 = packf2(s12, s13);
        r00 = addf2(r00, __shfl_xor_sync(0xffffffffu, r00, 16));
        r01 = addf2(r01, __shfl_xor_sync(0xffffffffu, r01, 16));
        r10 = addf2(r10, __shfl_xor_sync(0xffffffffu, r10, 16));
        r11 = addf2(r11, __shfl_xor_sync(0xffffffffu, r11, 16));
        if (kk == 0) {
            int gr0 = gate * 32 + 2 * lr;
            ull* gp = (ull*)(g_part + wks * 512 + gr0 * 4);
            gp[0] = r00; gp[1] = r01;
            gp[2] = r10; gp[3] = r11;
        }
        __syncthreads();

        // warps 8-11: prefetch next-step XW into the other xw_s buffer
        // (runs concurrently with the epilogue below; race-free: writes buf
        // (t+1)&1, epilogue reads buf t&1; next read is after next sync)
        if (pf && t + 1 < t_end) {
            int sn = dir ? (S_ - 2 - t) : (t + 1);
            long xb = (pf_row + sn) * GH + pf_col;
            #pragma unroll
            for (int g = 0; g < 4; g++) xw_s[(t + 1) & 1][g * 128 + pf_j] = XWd[xb + g * H_];
        }

        if (tid < 128) {
            const float* xwb = xw_s[t & 1];
            float gv[4];
            #pragma unroll
            for (int g = 0; g < 4; g++) {
                float sum = xwb[g * 128 + tid];
                int gi = (g * 32 + e_u) * 4 + e_b;
                #pragma unroll
                for (int ks = 0; ks < 4; ks++) sum += g_part[ks * 512 + gi];
                gv[g] = sum;
            }
            float c2 = hsig(gv[1]) * c_reg + hsig(gv[0]) * htanh(gv[2]);
            float h2 = hsig(gv[3]) * htanh(c2);
            bool upd = (s < e_len);
            float hn;
            if (upd) { c_reg = c2; hn = h2; }
            else     { hn = h_s[p * 1024 + e_b * 256 + e_gu]; }
            float q0 = hn;
            float q1 = __shfl_sync(0xffffffffu, hn, lane + 4);
            float q2 = __shfl_sync(0xffffffffu, hn, lane + 8);
            float q3 = __shfl_sync(0xffffffffu, hn, lane + 12);
            if ((e_u & 3) == 0) {
                uint32_t off = (uint32_t)((q * 1024 + e_b * 256 + e_gu) * 4);
                #pragma unroll
                for (int i = 0; i < CLUSTER; i++) {
                    int prr = (rot + i) & 7;
                    st_async_v4(peer_base[prr] + off, q0, q1, q2, q3,
                                peer_base[prr] + mbdq);
                }
            }
        }
        if (q) { mbar_wait(hs_base + mbd1, ph1); ph1 ^= 1; }
        else   { mbar_wait(hs_base + mbd0, ph0); ph0 ^= 1; }
    }

    // final h = contents of the last-written buffer (single store per value)
    {
        int qf = ((t_end - 1) & 1) ^ 1;
        if (tid < 128)
            g_hfinal[dir][bg * 4 + e_b][e_gu] = h_s[qf * 1024 + e_b * 256 + e_gu];
    }

    CLUSTER_SYNC();   // keep CTAs resident until all DSMEM traffic drained
}

// ---------------- FC + BN(batch axis) + relu + log_softmax(batch axis) ----
__global__ void final_kernel(const float* __restrict__ fc_w, const float* __restrict__ fc_b,
                             const float* __restrict__ gamma, const float* __restrict__ beta,
                             float* __restrict__ out) {
    __shared__ float wsh[2 * H_];
    __shared__ float lg[B_];
    int j = blockIdx.x;
    int tid = threadIdx.x, warp = tid >> 5, lane = tid & 31;
    for (int i = tid; i < 2 * H_; i += 256) wsh[i] = fc_w[j * 2 * H_ + i];
    __syncthreads();

    #pragma unroll
    for (int ii = 0; ii < 4; ii++) {
        int i = warp * 4 + ii;
        int dirc = i >> 4;
        int bb = (i & 15) * 2;
        const float* h0 = g_hfinal[dirc][bb];
        const float* h1 = g_hfinal[dirc][bb + 1];
        float p = 0.f;
        for (int k = lane; k < H_; k += 32) p += h0[k] * wsh[k] + h1[k] * wsh[H_ + k];
        #pragma unroll
        for (int o = 16; o; o >>= 1) p += __shfl_xor_sync(0xffffffffu, p, o);
        if (lane == 0) lg[i] = p + fc_b[j];
    }
    __syncthreads();

    if (warp == 0) {
        float v = lg[lane];
        float sum = v;
        #pragma unroll
        for (int o = 16; o; o >>= 1) sum += __shfl_xor_sync(0xffffffffu, sum, o);
        float mu = sum * (1.f / 32.f);
        float d = v - mu;
        float vs = d * d;
        #pragma unroll
        for (int o = 16; o; o >>= 1) vs += __shfl_xor_sync(0xffffffffu, vs, o);
        float var = vs * (1.f / 32.f);
        float y = gamma[j] * d * rsqrtf(var + 1e-5f) + beta[j];
        y = fmaxf(y, 0.f);
        float mx = y;
        #pragma unroll
        for (int o = 16; o; o >>= 1) mx = fmaxf(mx, __shfl_xor_sync(0xffffffffu, mx, o));
        float ev = expf(y - mx);
        float se = ev;
        #pragma unroll
        for (int o = 16; o; o >>= 1) se += __shfl_xor_sync(0xffffffffu, se, o);
        out[lane * OUTD + j] = y - mx - logf(se);
    }
}

// ---------------- launch ----------------
extern "C" void kernel_launch(void* const* d_in, const int* in_sizes, int n_in,
                              void* d_out, int out_size) {
    const int*           x      = (const int*)d_in[0];
    const unsigned char* xmask  = (const unsigned char*)d_in[1];
    const float*         xfeat  = (const float*)d_in[2];
    const int*           lens   = (const int*)d_in[3];
    const float* emb    = (const float*)d_in[6];
    const float* attn_w = (const float*)d_in[7];
    const float* attn_b = (const float*)d_in[8];
    const float* wih_f  = (const float*)d_in[9];
    const float* whh_f  = (const float*)d_in[10];
    const float* bih_f  = (const float*)d_in[11];
    const float* bhh_f  = (const float*)d_in[12];
    const float* wih_b  = (const float*)d_in[13];
    const float* whh_b  = (const float*)d_in[14];
    const float* bih_b  = (const float*)d_in[15];
    const float* bhh_b  = (const float*)d_in[16];
    const float* fc_w   = (const float*)d_in[17];
    const float* fc_b   = (const float*)d_in[18];
    const float* bn_g   = (const float*)d_in[19];
    const float* bn_b   = (const float*)d_in[20];

    const int smem1 = (T_ * H_ + 128) * 4;
    cudaFuncSetAttribute(stage1_kernel, cudaFuncAttributeMaxDynamicSharedMemorySize, smem1);

    detect_mask_kernel<<<1, 256>>>((const uint4*)xmask, (B_ * S_ * T_) / 16);
    stage1_kernel<<<B_ * S_, 256, smem1>>>(x, xmask, xfeat, emb, attn_w, attn_b);
    xw_gemm_kernel<<<dim3(1280 / 64, GH / 128, 2), 256>>>(wih_f, wih_b, bih_f, bhh_f,
                                                          bih_b, bhh_b, lens);
    lstm_kernel<<<128, 512>>>(whh_f, whh_b, lens);
    final_kernel<<<OUTD, 256>>>(fc_w, fc_b, bn_g, bn_b, (float*)d_out);
}

// round 13
// speedup vs baseline: 1.0476x; 1.0476x over previous
#include <cuda_runtime.h>
#include <math.h>
#include <stdint.h>

#define S_  40
#define B_  32
#define T_  60
#define H_  256
#define F_  64
#define DIN 320
#define OUTD 128
#define GH  1024   // 4*H
#define CLUSTER 8

typedef unsigned long long ull;

// ---------------- device scratch ----------------
__device__ float g_sen[B_ * S_ * DIN];          // sen[b][s][0:320]
__device__ float g_XW[2][B_ * S_ * GH];         // [dir][b*S+s][1024]
__device__ float g_hfinal[2][B_][H_];
__device__ int g_mask_u8;

// ---------------- f32x2 helpers ----------------
__device__ __forceinline__ ull packf2(float a, float b) {
    ull r; asm("mov.b64 %0, {%1,%2};" : "=l"(r) : "f"(a), "f"(b)); return r;
}
__device__ __forceinline__ ull fma2(ull a, ull b, ull c) {
    ull d; asm("fma.rn.f32x2 %0, %1, %2, %3;" : "=l"(d) : "l"(a), "l"(b), "l"(c)); return d;
}
__device__ __forceinline__ ull addf2(ull a, ull b) {
    ull d; asm("add.rn.f32x2 %0, %1, %2;" : "=l"(d) : "l"(a), "l"(b)); return d;
}
__device__ __forceinline__ void unpackf2(ull v, float& lo, float& hi) {
    asm("mov.b64 {%0,%1}, %2;" : "=f"(lo), "=f"(hi) : "l"(v));
}
__device__ __forceinline__ uint32_t smem_u32(const void* p) {
    uint32_t a;
    asm("{ .reg .u64 t; cvta.to.shared.u64 t, %1; cvt.u32.u64 %0, t; }" : "=r"(a) : "l"(p));
    return a;
}
__device__ __forceinline__ uint32_t mapa_u32(uint32_t saddr, int rank) {
    uint32_t r;
    asm("mapa.shared::cluster.u32 %0, %1, %2;" : "=r"(r) : "r"(saddr), "r"(rank));
    return r;
}
__device__ __forceinline__ void st_async_v4(uint32_t daddr, float a, float b, float c, float d,
                                            uint32_t mbar) {
    asm volatile(
        "st.async.weak.shared::cluster.mbarrier::complete_tx::bytes.v4.f32 "
        "[%0], {%1,%2,%3,%4}, [%5];"
        :: "r"(daddr), "f"(a), "f"(b), "f"(c), "f"(d), "r"(mbar) : "memory");
}
__device__ __forceinline__ void mbar_init(uint32_t mbar, uint32_t cnt) {
    asm volatile("mbarrier.init.shared.b64 [%0], %1;" :: "r"(mbar), "r"(cnt) : "memory");
}
__device__ __forceinline__ void mbar_expect_tx(uint32_t mbar, uint32_t bytes) {
    asm volatile("mbarrier.arrive.expect_tx.shared.b64 _, [%0], %1;"
                 :: "r"(mbar), "r"(bytes) : "memory");
}
__device__ __forceinline__ void mbar_wait(uint32_t mbar, uint32_t parity) {
    asm volatile(
        "{\n\t.reg .pred P;\n\t"
        "WAIT_%=:\n\t"
        "mbarrier.try_wait.parity.acquire.cluster.shared::cta.b64 P, [%0], %1;\n\t"
        "@!P bra WAIT_%=;\n\t}"
        :: "r"(mbar), "r"(parity) : "memory");
}
#define CLUSTER_ARRIVE() asm volatile("barrier.cluster.arrive.aligned;" ::: "memory")
#define CLUSTER_WAIT()   asm volatile("barrier.cluster.wait.aligned;"   ::: "memory")
#define CLUSTER_SYNC() do { CLUSTER_ARRIVE(); CLUSTER_WAIT(); } while (0)

__device__ __forceinline__ float htanh(float x) {
    float y; asm("tanh.approx.f32 %0, %1;" : "=f"(y) : "f"(x)); return y;
}
__device__ __forceinline__ float hsig(float x) {
    return 0.5f * htanh(0.5f * x) + 0.5f;
}
__device__ __forceinline__ uint32_t to_tf32(float f) {
    uint32_t u; asm("cvt.rna.tf32.f32 %0, %1;" : "=r"(u) : "f"(f)); return u;
}

// ---------------- mask dtype detection ----------------
__global__ void detect_mask_kernel(const uint4* __restrict__ m, int nwords4) {
    __shared__ int found;
    if (threadIdx.x == 0) found = 0;
    __syncthreads();
    for (int i = threadIdx.x; i < nwords4; i += blockDim.x) {
        uint4 v = m[i];
        if ((v.x | v.y | v.z | v.w) & 0xFFFFFF00u) { found = 1; break; }
    }
    __syncthreads();
    if (threadIdx.x == 0) g_mask_u8 = found;
}

// ---------------- stage 1: gather + attention pooling + feature sum ----
// Skips (b,s) with s >= group-max(len): those sen rows are only consumed by
// XW rows the LSTM never reads (same predicate as the gemm tile skip).
__global__ void stage1_kernel(const int* __restrict__ x,
                              const unsigned char* __restrict__ xmask,
                              const float* __restrict__ xfeat,
                              const float* __restrict__ emb,
                              const float* __restrict__ attn_w,
                              const float* __restrict__ attn_b,
                              const int* __restrict__ lens) {
    extern __shared__ float sm[];
    float* e_s     = sm;
    float* score_s = sm + T_ * H_;
    float* alpha_s = score_s + 64;

    int bs = blockIdx.x;
    int b = bs / S_, s = bs % S_;
    if (s >= lens[(b >> 2) << 2]) return;   // dead row, never consumed
    int tid = threadIdx.x, warp = tid >> 5, lane = tid & 31;
    int u8 = g_mask_u8;
    long base = (long)(b * S_ + s) * T_;
    float ab = attn_b[0];

    for (int t = warp; t < T_; t += 8) {
        int xi = x[base + t];
        long mi = base + t;
        unsigned char mv = u8 ? xmask[mi] : xmask[mi * 4];
        int valid = (mv == 0);
        float4 v0, v1;
        if (valid) {
            const float4* er = (const float4*)(emb + (long)xi * H_);
            v0 = er[lane]; v1 = er[lane + 32];
        } else {
            v0 = make_float4(0.f, 0.f, 0.f, 0.f); v1 = v0;
        }
        float4* ed = (float4*)(e_s + t * H_);
        ed[lane] = v0; ed[lane + 32] = v1;
        const float4* aw = (const float4*)attn_w;
        float4 w0 = aw[lane], w1 = aw[lane + 32];
        float p = v0.x*w0.x + v0.y*w0.y + v0.z*w0.z + v0.w*w0.w
                + v1.x*w1.x + v1.y*w1.y + v1.z*w1.z + v1.w*w1.w;
        #pragma unroll
        for (int o = 16; o; o >>= 1) p += __shfl_xor_sync(0xffffffffu, p, o);
        if (lane == 0) score_s[t] = valid ? (p + ab) : -1e30f;
    }
    __syncthreads();

    if (warp == 0) {
        float s0 = (lane < T_)      ? score_s[lane]      : -1e30f;
        float s1 = (lane + 32 < T_) ? score_s[lane + 32] : -1e30f;
        float mx = fmaxf(s0, s1);
        #pragma unroll
        for (int o = 16; o; o >>= 1) mx = fmaxf(mx, __shfl_xor_sync(0xffffffffu, mx, o));
        float e0 = (s0 > -1e29f) ? expf(s0 - mx) : 0.f;
        float e1 = (s1 > -1e29f) ? expf(s1 - mx) : 0.f;
        float sum = e0 + e1;
        #pragma unroll
        for (int o = 16; o; o >>= 1) sum += __shfl_xor_sync(0xffffffffu, sum, o);
        float inv = (mx > -1e29f) ? (1.f / sum) : 0.f;
        if (lane < T_)      alpha_s[lane]      = e0 * inv;
        if (lane + 32 < T_) alpha_s[lane + 32] = e1 * inv;
    }
    __syncthreads();

    float acc = 0.f;
    #pragma unroll 4
    for (int t = 0; t < T_; t++) acc += alpha_s[t] * e_s[t * H_ + tid];
    g_sen[(b * S_ + s) * DIN + tid] = acc;

    if (tid < F_) {
        float fa = 0.f;
        const float* fp = xfeat + base * F_ + tid;
        #pragma unroll 4
        for (int t = 0; t < T_; t++)
            if (score_s[t] > -1e29f) fa += fp[t * F_];
        g_sen[(b * S_ + s) * DIN + H_ + tid] = fa;
    }
}

// ---------------- XW GEMM via tf32 tensor cores, 64-row tiles + lens skip ---
#define PA 36
#define PW 36
__global__ void __launch_bounds__(256) xw_gemm_kernel(
    const float* __restrict__ wf, const float* __restrict__ wb,
    const float* __restrict__ bih_f, const float* __restrict__ bhh_f,
    const float* __restrict__ bih_b, const float* __restrict__ bhh_b,
    const int* __restrict__ lens) {
    int m0 = blockIdx.x * 64;
    {
        bool live = false;
        int b0 = m0 / S_, b1 = (m0 + 63) / S_;
        for (int b = b0; b <= b1 && b < B_; b++) {
            int glen = lens[(b >> 2) << 2];          // group max (sorted desc)
            int row_lo = b * S_;
            int s_start = (m0 > row_lo) ? (m0 - row_lo) : 0;
            if (row_lo < m0 + 64 && s_start < glen) { live = true; break; }
        }
        if (!live) return;
    }
    __shared__ uint32_t As[64 * PA];
    __shared__ uint32_t Ws[128 * PW];
    int dir = blockIdx.z;
    const float* W  = dir ? wb : wf;
    const float* b1p = dir ? bih_b : bih_f;
    const float* b2p = dir ? bhh_b : bhh_f;
    int n0 = blockIdx.y * 128;
    int tid = threadIdx.x, lane = tid & 31, warp = tid >> 5;
    int wm = warp & 1, wn = warp >> 1;
    int g = lane >> 2, tq = lane & 3;

    float acc[2][4][4];
    #pragma unroll
    for (int mi = 0; mi < 2; mi++)
        #pragma unroll
        for (int ni = 0; ni < 4; ni++)
            #pragma unroll
            for (int c = 0; c < 4; c++) acc[mi][ni][c] = 0.f;

    for (int kt = 0; kt < DIN; kt += 32) {
        #pragma unroll
        for (int l = 0; l < 2; l++) {
            int i = tid + l * 256;
            int r = i >> 3, c4 = (i & 7) * 4;
            float4 v = *(const float4*)(g_sen + (long)(m0 + r) * DIN + kt + c4);
            uint32_t* d = As + r * PA + c4;
            d[0] = to_tf32(v.x); d[1] = to_tf32(v.y);
            d[2] = to_tf32(v.z); d[3] = to_tf32(v.w);
        }
        #pragma unroll
        for (int l = 0; l < 4; l++) {
            int i = tid + l * 256;
            int r = i >> 3, c4 = (i & 7) * 4;
            float4 v = *(const float4*)(W + (long)(n0 + r) * DIN + kt + c4);
            uint32_t* d = Ws + r * PW + c4;
            d[0] = to_tf32(v.x); d[1] = to_tf32(v.y);
            d[2] = to_tf32(v.z); d[3] = to_tf32(v.w);
        }
        __syncthreads();

        #pragma unroll
        for (int ks = 0; ks < 4; ks++) {
            int kb = ks * 8;
            uint32_t a[2][4];
            #pragma unroll
            for (int mi = 0; mi < 2; mi++) {
                int row = wm * 32 + mi * 16 + g;
                a[mi][0] = As[row * PA + kb + tq];
                a[mi][1] = As[(row + 8) * PA + kb + tq];
                a[mi][2] = As[row * PA + kb + tq + 4];
                a[mi][3] = As[(row + 8) * PA + kb + tq + 4];
            }
            uint32_t bfr[4][2];
            #pragma unroll
            for (int ni = 0; ni < 4; ni++) {
                int col = wn * 32 + ni * 8 + g;
                bfr[ni][0] = Ws[col * PW + kb + tq];
                bfr[ni][1] = Ws[col * PW + kb + tq + 4];
            }
            #pragma unroll
            for (int mi = 0; mi < 2; mi++)
                #pragma unroll
                for (int ni = 0; ni < 4; ni++) {
                    float* c = acc[mi][ni];
                    asm("mma.sync.aligned.m16n8k8.row.col.f32.tf32.tf32.f32 "
                        "{%0,%1,%2,%3}, {%4,%5,%6,%7}, {%8,%9}, {%0,%1,%2,%3};"
                        : "+f"(c[0]), "+f"(c[1]), "+f"(c[2]), "+f"(c[3])
                        : "r"(a[mi][0]), "r"(a[mi][1]), "r"(a[mi][2]), "r"(a[mi][3]),
                          "r"(bfr[ni][0]), "r"(bfr[ni][1]));
                }
        }
        __syncthreads();
    }

    float* C = g_XW[dir];
    #pragma unroll
    for (int ni = 0; ni < 4; ni++) {
        int col = n0 + wn * 32 + ni * 8 + 2 * tq;
        float bb0 = b1p[col] + b2p[col];
        float bb1 = b1p[col + 1] + b2p[col + 1];
        #pragma unroll
        for (int mi = 0; mi < 2; mi++) {
            int row = m0 + wm * 32 + mi * 16 + g;
            *(float2*)(C + (long)row * GH + col) =
                make_float2(acc[mi][ni][0] + bb0, acc[mi][ni][1] + bb1);
            *(float2*)(C + (long)(row + 8) * GH + col) =
                make_float2(acc[mi][ni][2] + bb0, acc[mi][ni][3] + bb1);
        }
    }
}

// ---------------- clustered bidirectional LSTM: split lo/hi h barriers -----
// R11 structure, but the per-step inbound barrier is split into lo (units
// 0-127, ranks 0-3) and hi (units 128-255, ranks 4-7) halves, 2048B each.
// Warps with wks<2 consume K in [0,128) -> wait lo only; wks>=2 wait hi only.
// Epilogue cross-half reads are ordered by the mid-step __syncthreads.
__global__ void __launch_bounds__(512, 1) __cluster_dims__(CLUSTER, 1, 1)
lstm_kernel(const float* __restrict__ whh_f, const float* __restrict__ whh_b,
            const int* __restrict__ lens) {
    __shared__ __align__(16) float h_s[2 * 1024];     // [p][b:4][k:256]
    __shared__ __align__(16) float g_part[4 * 512];   // [wks][gr:128][b:4]
    __shared__ __align__(8)  ull  mbar[4];            // [buf][half]

    int dir = blockIdx.x >> 6;
    int bg  = (blockIdx.x >> 3) & 7;
    int rank; asm("mov.u32 %0, %%cluster_ctarank;" : "=r"(rank));
    int tid = threadIdx.x, lane = tid & 31, warp = tid >> 5;
    int wks = warp & 3, gate = warp >> 2;
    int kk = lane >> 4, lr = lane & 15;
    const float* whh = dir ? whh_b : whh_f;

    int gu0 = 32 * rank + 2 * lr;
    int kbase = 64 * wks + 32 * kk;
    ull wp0[16], wp1[16];
    {
        const ulonglong2* w0p = (const ulonglong2*)(whh + (long)(gate * H_ + gu0) * H_ + kbase);
        const ulonglong2* w1p = (const ulonglong2*)(whh + (long)(gate * H_ + gu0 + 1) * H_ + kbase);
        #pragma unroll
        for (int q = 0; q < 8; q++) {
            ulonglong2 v0 = w0p[q], v1 = w1p[q];
            wp0[2*q] = v0.x; wp0[2*q+1] = v0.y;
            wp1[2*q] = v1.x; wp1[2*q+1] = v1.y;
        }
    }
    for (int i = tid; i < 2048; i += 512) h_s[i] = 0.f;

    uint32_t hs_base = smem_u32(h_s);
    uint32_t mbd[4];
    #pragma unroll
    for (int i = 0; i < 4; i++) mbd[i] = smem_u32(&mbar[i]) - hs_base;
    if (tid == 0) {
        #pragma unroll
        for (int i = 0; i < 4; i++) mbar_init(hs_base + mbd[i], 1);
    }

    int e_u = tid >> 2, e_b = tid & 3;           // epilogue identity (tid<128)
    int e_gu = 32 * rank + e_u;
    int e_len = lens[bg * 4 + e_b];
    int len_grp = lens[bg * 4];                  // group max (lens sorted descending)
    float c_reg = 0.f;
    const float* XWd = g_XW[dir];

    uint32_t peer_base[CLUSTER];
    #pragma unroll
    for (int prr = 0; prr < CLUSTER; prr++) peer_base[prr] = mapa_u32(hs_base, prr);
    int rot = (tid >> 2) & 7;

    // my consumed half (by K slice) and my produced half (by rank)
    int myhalf = (wks < 2) ? 0 : 1;
    uint32_t mbd_my[2]  = { mbd[0 * 2 + myhalf],      mbd[1 * 2 + myhalf] };
    int rh = rank >> 2;
    uint32_t mbd_st[2]  = { mbd[0 * 2 + rh],          mbd[1 * 2 + rh] };

    CLUSTER_SYNC();   // zero-init h + mbar init visible cluster-wide

    int t0    = dir ? (S_ - len_grp) : 0;
    int t_end = dir ? S_ : len_grp;
    uint32_t ph[2] = {0, 0};                     // parity per buffer (my half)

    float xw[4] = {0.f, 0.f, 0.f, 0.f};
    if (tid < 128) {
        int s0 = dir ? (len_grp - 1) : 0;
        long xb = ((long)(bg * 4 + e_b) * S_ + s0) * GH + e_gu;
        #pragma unroll
        for (int g = 0; g < 4; g++) xw[g] = XWd[xb + g * H_];
    }

    for (int t = t0; t < t_end; t++) {
        int s = dir ? (S_ - 1 - t) : t;
        int p = t & 1;
        int q = p ^ 1;
        if (tid == 0) {
            mbar_expect_tx(hs_base + mbd[q * 2],     2048);
            mbar_expect_tx(hs_base + mbd[q * 2 + 1], 2048);
        }
        const float* hb = h_s + p * 1024 + kbase;

        ull a00=0, a01=0, a02=0, a03=0;
        ull a10=0, a11=0, a12=0, a13=0;
        #pragma unroll
        for (int i = 0; i < 8; i++) {
            ulonglong2 h0 = *(const ulonglong2*)(hb + 4*i);
            ulonglong2 h1 = *(const ulonglong2*)(hb + 256 + 4*i);
            ulonglong2 h2 = *(const ulonglong2*)(hb + 512 + 4*i);
            ulonglong2 h3 = *(const ulonglong2*)(hb + 768 + 4*i);
            ull wa = wp0[2*i], wb = wp0[2*i+1];
            ull wc = wp1[2*i], wd = wp1[2*i+1];
            a00 = fma2(wa, h0.x, a00); a00 = fma2(wb, h0.y, a00);
            a01 = fma2(wa, h1.x, a01); a01 = fma2(wb, h1.y, a01);
            a02 = fma2(wa, h2.x, a02); a02 = fma2(wb, h2.y, a02);
            a03 = fma2(wa, h3.x, a03); a03 = fma2(wb, h3.y, a03);
            a10 = fma2(wc, h0.x, a10); a10 = fma2(wd, h0.y, a10);
            a11 = fma2(wc, h1.x, a11); a11 = fma2(wd, h1.y, a11);
            a12 = fma2(wc, h2.x, a12); a12 = fma2(wd, h2.y, a12);
            a13 = fma2(wc, h3.x, a13); a13 = fma2(wd, h3.y, a13);
        }
        float l0, l1, s00, s01, s02, s03, s10, s11, s12, s13;
        unpackf2(a00, l0, l1); s00 = l0 + l1;
        unpackf2(a01, l0, l1); s01 = l0 + l1;
        unpackf2(a02, l0, l1); s02 = l0 + l1;
        unpackf2(a03, l0, l1); s03 = l0 + l1;
        unpackf2(a10, l0, l1); s10 = l0 + l1;
        unpackf2(a11, l0, l1); s11 = l0 + l1;
        unpackf2(a12, l0, l1); s12 = l0 + l1;
        unpackf2(a13, l0, l1); s13 = l0 + l1;
        ull r00 = packf2(s00, s01), r01 = packf2(s02, s03);
        ull r10 = packf2(s10, s11), r11 = packf2(s12, s13);
        r00 = addf2(r00, __shfl_xor_sync(0xffffffffu, r00, 16));
        r01 = addf2(r01, __shfl_xor_sync(0xffffffffu, r01, 16));
        r10 = addf2(r10, __shfl_xor_sync(0xffffffffu, r10, 16));
        r11 = addf2(r11, __shfl_xor_sync(0xffffffffu, r11, 16));
        if (kk == 0) {
            int gr0 = gate * 32 + 2 * lr;
            ull* gp = (ull*)(g_part + wks * 512 + gr0 * 4);
            gp[0] = r00; gp[1] = r01;
            gp[2] = r10; gp[3] = r11;
        }
        __syncthreads();

        if (tid < 128) {
            float gv[4];
            #pragma unroll
            for (int g = 0; g < 4; g++) {
                float sum = xw[g];
                int gi = (g * 32 + e_u) * 4 + e_b;
                #pragma unroll
                for (int ks = 0; ks < 4; ks++) sum += g_part[ks * 512 + gi];
                gv[g] = sum;
            }
            float c2 = hsig(gv[1]) * c_reg + hsig(gv[0]) * htanh(gv[2]);
            float h2 = hsig(gv[3]) * htanh(c2);
            bool upd = (s < e_len);
            float hn;
            if (upd) { c_reg = c2; hn = h2; }
            else     { hn = h_s[p * 1024 + e_b * 256 + e_gu]; }
            float q0 = hn;
            float q1 = __shfl_sync(0xffffffffu, hn, lane + 4);
            float q2 = __shfl_sync(0xffffffffu, hn, lane + 8);
            float q3 = __shfl_sync(0xffffffffu, hn, lane + 12);
            if ((e_u & 3) == 0) {
                uint32_t off = (uint32_t)((q * 1024 + e_b * 256 + e_gu) * 4);
                uint32_t mst = mbd_st[q];
                #pragma unroll
                for (int i = 0; i < CLUSTER; i++) {
                    int prr = (rot + i) & 7;
                    st_async_v4(peer_base[prr] + off, q0, q1, q2, q3,
                                peer_base[prr] + mst);
                }
            }
        }
        // prefetch next-step XW while peers' stores are in flight
        if (tid < 128 && t + 1 < t_end) {
            int sn = dir ? (S_ - 2 - t) : (t + 1);
            long xb = ((long)(bg * 4 + e_b) * S_ + sn) * GH + e_gu;
            #pragma unroll
            for (int g = 0; g < 4; g++) xw[g] = XWd[xb + g * H_];
        }
        // wait only on the half this warp consumes next step
        mbar_wait(hs_base + mbd_my[q], ph[q]);
        ph[q] ^= 1;
    }

    // final h = contents of the last-written buffer; sync first so cross-half
    // visibility (acquired by the other half's waiters) reaches these warps
    __syncthreads();
    {
        int qf = ((t_end - 1) & 1) ^ 1;
        if (tid < 128)
            g_hfinal[dir][bg * 4 + e_b][e_gu] = h_s[qf * 1024 + e_b * 256 + e_gu];
    }

    CLUSTER_SYNC();   // keep CTAs resident until all DSMEM traffic drained
}

// ---------------- FC + BN(batch axis) + relu + log_softmax(batch axis) ----
__global__ void final_kernel(const float* __restrict__ fc_w, const float* __restrict__ fc_b,
                             const float* __restrict__ gamma, const float* __restrict__ beta,
                             float* __restrict__ out) {
    __shared__ float wsh[2 * H_];
    __shared__ float lg[B_];
    int j = blockIdx.x;
    int tid = threadIdx.x, warp = tid >> 5, lane = tid & 31;
    for (int i = tid; i < 2 * H_; i += 256) wsh[i] = fc_w[j * 2 * H_ + i];
    __syncthreads();

    #pragma unroll
    for (int ii = 0; ii < 4; ii++) {
        int i = warp * 4 + ii;
        int dirc = i >> 4;
        int bb = (i & 15) * 2;
        const float* h0 = g_hfinal[dirc][bb];
        const float* h1 = g_hfinal[dirc][bb + 1];
        float p = 0.f;
        for (int k = lane; k < H_; k += 32) p += h0[k] * wsh[k] + h1[k] * wsh[H_ + k];
        #pragma unroll
        for (int o = 16; o; o >>= 1) p += __shfl_xor_sync(0xffffffffu, p, o);
        if (lane == 0) lg[i] = p + fc_b[j];
    }
    __syncthreads();

    if (warp == 0) {
        float v = lg[lane];
        float sum = v;
        #pragma unroll
        for (int o = 16; o; o >>= 1) sum += __shfl_xor_sync(0xffffffffu, sum, o);
        float mu = sum * (1.f / 32.f);
        float d = v - mu;
        float vs = d * d;
        #pragma unroll
        for (int o = 16; o; o >>= 1) vs += __shfl_xor_sync(0xffffffffu, vs, o);
        float var = vs * (1.f / 32.f);
        float y = gamma[j] * d * rsqrtf(var + 1e-5f) + beta[j];
        y = fmaxf(y, 0.f);
        float mx = y;
        #pragma unroll
        for (int o = 16; o; o >>= 1) mx = fmaxf(mx, __shfl_xor_sync(0xffffffffu, mx, o));
        float ev = expf(y - mx);
        float se = ev;
        #pragma unroll
        for (int o = 16; o; o >>= 1) se += __shfl_xor_sync(0xffffffffu, se, o);
        out[lane * OUTD + j] = y - mx - logf(se);
    }
}

// ---------------- launch ----------------
extern "C" void kernel_launch(void* const* d_in, const int* in_sizes, int n_in,
                              void* d_out, int out_size) {
    const int*           x      = (const int*)d_in[0];
    const unsigned char* xmask  = (const unsigned char*)d_in[1];
    const float*         xfeat  = (const float*)d_in[2];
    const int*           lens   = (const int*)d_in[3];
    const float* emb    = (const float*)d_in[6];
    const float* attn_w = (const float*)d_in[7];
    const float* attn_b = (const float*)d_in[8];
    const float* wih_f  = (const float*)d_in[9];
    const float* whh_f  = (const float*)d_in[10];
    const float* bih_f  = (const float*)d_in[11];
    const float* bhh_f  = (const float*)d_in[12];
    const float* wih_b  = (const float*)d_in[13];
    const float* whh_b  = (const float*)d_in[14];
    const float* bih_b  = (const float*)d_in[15];
    const float* bhh_b  = (const float*)d_in[16];
    const float* fc_w   = (const float*)d_in[17];
    const float* fc_b   = (const float*)d_in[18];
    const float* bn_g   = (const float*)d_in[19];
    const float* bn_b   = (const float*)d_in[20];

    const int smem1 = (T_ * H_ + 128) * 4;
    cudaFuncSetAttribute(stage1_kernel, cudaFuncAttributeMaxDynamicSharedMemorySize, smem1);

    detect_mask_kernel<<<1, 256>>>((const uint4*)xmask, (B_ * S_ * T_) / 16);
    stage1_kernel<<<B_ * S_, 256, smem1>>>(x, xmask, xfeat, emb, attn_w, attn_b, lens);
    xw_gemm_kernel<<<dim3(1280 / 64, GH / 128, 2), 256>>>(wih_f, wih_b, bih_f, bhh_f,
                                                          bih_b, bhh_b, lens);
    lstm_kernel<<<128, 512>>>(whh_f, whh_b, lens);
    final_kernel<<<OUTD, 256>>>(fc_w, fc_b, bn_g, bn_b, (float*)d_out);
}

// round 14
// speedup vs baseline: 1.0819x; 1.0328x over previous
#include <cuda_runtime.h>
#include <math.h>
#include <stdint.h>

#define S_  40
#define B_  32
#define T_  60
#define H_  256
#define F_  64
#define DIN 320
#define OUTD 128
#define GH  1024   // 4*H
#define CLUSTER 8

typedef unsigned long long ull;

// ---------------- device scratch ----------------
__device__ float g_sen[B_ * S_ * DIN];          // sen[b][s][0:320]
__device__ float g_XW[2][B_ * S_ * GH];         // [dir][b*S+s][1024]
__device__ float g_hfinal[2][B_][H_];
__device__ int g_mask_u8;

// ---------------- f32x2 helpers ----------------
__device__ __forceinline__ ull packf2(float a, float b) {
    ull r; asm("mov.b64 %0, {%1,%2};" : "=l"(r) : "f"(a), "f"(b)); return r;
}
__device__ __forceinline__ ull fma2(ull a, ull b, ull c) {
    ull d; asm("fma.rn.f32x2 %0, %1, %2, %3;" : "=l"(d) : "l"(a), "l"(b), "l"(c)); return d;
}
__device__ __forceinline__ ull addf2(ull a, ull b) {
    ull d; asm("add.rn.f32x2 %0, %1, %2;" : "=l"(d) : "l"(a), "l"(b)); return d;
}
__device__ __forceinline__ void unpackf2(ull v, float& lo, float& hi) {
    asm("mov.b64 {%0,%1}, %2;" : "=f"(lo), "=f"(hi) : "l"(v));
}
__device__ __forceinline__ uint32_t smem_u32(const void* p) {
    uint32_t a;
    asm("{ .reg .u64 t; cvta.to.shared.u64 t, %1; cvt.u32.u64 %0, t; }" : "=r"(a) : "l"(p));
    return a;
}
__device__ __forceinline__ uint32_t mapa_u32(uint32_t saddr, int rank) {
    uint32_t r;
    asm("mapa.shared::cluster.u32 %0, %1, %2;" : "=r"(r) : "r"(saddr), "r"(rank));
    return r;
}
__device__ __forceinline__ void st_async_v4(uint32_t daddr, float a, float b, float c, float d,
                                            uint32_t mbar) {
    asm volatile(
        "st.async.weak.shared::cluster.mbarrier::complete_tx::bytes.v4.f32 "
        "[%0], {%1,%2,%3,%4}, [%5];"
        :: "r"(daddr), "f"(a), "f"(b), "f"(c), "f"(d), "r"(mbar) : "memory");
}
__device__ __forceinline__ void mbar_init(uint32_t mbar, uint32_t cnt) {
    asm volatile("mbarrier.init.shared.b64 [%0], %1;" :: "r"(mbar), "r"(cnt) : "memory");
}
__device__ __forceinline__ void mbar_expect_tx(uint32_t mbar, uint32_t bytes) {
    asm volatile("mbarrier.arrive.expect_tx.shared.b64 _, [%0], %1;"
                 :: "r"(mbar), "r"(bytes) : "memory");
}
__device__ __forceinline__ void mbar_wait(uint32_t mbar, uint32_t parity) {
    asm volatile(
        "{\n\t.reg .pred P;\n\t"
        "WAIT_%=:\n\t"
        "mbarrier.try_wait.parity.acquire.cluster.shared::cta.b64 P, [%0], %1;\n\t"
        "@!P bra WAIT_%=;\n\t}"
        :: "r"(mbar), "r"(parity) : "memory");
}
#define CLUSTER_ARRIVE() asm volatile("barrier.cluster.arrive.aligned;" ::: "memory")
#define CLUSTER_WAIT()   asm volatile("barrier.cluster.wait.aligned;"   ::: "memory")
#define CLUSTER_SYNC() do { CLUSTER_ARRIVE(); CLUSTER_WAIT(); } while (0)

__device__ __forceinline__ float htanh(float x) {
    float y; asm("tanh.approx.f32 %0, %1;" : "=f"(y) : "f"(x)); return y;
}
__device__ __forceinline__ float hsig(float x) {
    return 0.5f * htanh(0.5f * x) + 0.5f;
}
__device__ __forceinline__ uint32_t to_tf32(float f) {
    uint32_t u; asm("cvt.rna.tf32.f32 %0, %1;" : "=r"(u) : "f"(f)); return u;
}

// ---------------- mask dtype detection ----------------
__global__ void detect_mask_kernel(const uint4* __restrict__ m, int nwords4) {
    __shared__ int found;
    if (threadIdx.x == 0) found = 0;
    __syncthreads();
    for (int i = threadIdx.x; i < nwords4; i += blockDim.x) {
        uint4 v = m[i];
        if ((v.x | v.y | v.z | v.w) & 0xFFFFFF00u) { found = 1; break; }
    }
    __syncthreads();
    if (threadIdx.x == 0) g_mask_u8 = found;
}

// ---------------- stage 1: attention pooling, L1-resident two-pass ----------
// No smem staging of embedding rows: phase 1 gathers rows (they land in L1),
// phase 2 re-reads them coalesced from L1. smem = scores/alpha/token ids only
// (~600B) -> thread-limited occupancy (8 CTAs/SM), all live CTAs in ~1 wave.
__global__ void __launch_bounds__(256) stage1_kernel(
    const int* __restrict__ x,
    const unsigned char* __restrict__ xmask,
    const float* __restrict__ xfeat,
    const float* __restrict__ emb,
    const float* __restrict__ attn_w,
    const float* __restrict__ attn_b,
    const int* __restrict__ lens) {
    __shared__ float score_s[64];
    __shared__ float alpha_s[64];
    __shared__ int   xs_s[64];

    int bs = blockIdx.x;
    int b = bs / S_, s = bs % S_;
    if (s >= lens[(b >> 2) << 2]) return;   // dead row, never consumed
    int tid = threadIdx.x, warp = tid >> 5, lane = tid & 31;
    int u8 = g_mask_u8;
    long base = (long)(b * S_ + s) * T_;
    float ab = attn_b[0];

    // phase 1: scores (warp per token); rows pulled through L1
    const float4* aw = (const float4*)attn_w;
    float4 w0 = aw[lane], w1 = aw[lane + 32];
    for (int t = warp; t < T_; t += 8) {
        int xi = x[base + t];
        long mi = base + t;
        unsigned char mv = u8 ? xmask[mi] : xmask[mi * 4];
        int valid = (mv == 0);
        float p = 0.f;
        if (valid) {
            const float4* er = (const float4*)(emb + (long)xi * H_);
            float4 v0 = er[lane], v1 = er[lane + 32];
            p = v0.x*w0.x + v0.y*w0.y + v0.z*w0.z + v0.w*w0.w
              + v1.x*w1.x + v1.y*w1.y + v1.z*w1.z + v1.w*w1.w;
        }
        #pragma unroll
        for (int o = 16; o; o >>= 1) p += __shfl_xor_sync(0xffffffffu, p, o);
        if (lane == 0) {
            score_s[t] = valid ? (p + ab) : -1e30f;
            xs_s[t] = xi;
        }
    }
    __syncthreads();

    // softmax over tokens (warp 0)
    if (warp == 0) {
        float s0 = (lane < T_)      ? score_s[lane]      : -1e30f;
        float s1 = (lane + 32 < T_) ? score_s[lane + 32] : -1e30f;
        float mx = fmaxf(s0, s1);
        #pragma unroll
        for (int o = 16; o; o >>= 1) mx = fmaxf(mx, __shfl_xor_sync(0xffffffffu, mx, o));
        float e0 = (s0 > -1e29f) ? expf(s0 - mx) : 0.f;
        float e1 = (s1 > -1e29f) ? expf(s1 - mx) : 0.f;
        float sum = e0 + e1;
        #pragma unroll
        for (int o = 16; o; o >>= 1) sum += __shfl_xor_sync(0xffffffffu, sum, o);
        float inv = (mx > -1e29f) ? (1.f / sum) : 0.f;
        if (lane < T_)      alpha_s[lane]      = e0 * inv;
        if (lane + 32 < T_) alpha_s[lane + 32] = e1 * inv;
    }
    __syncthreads();

    // phase 2: emb_part — thread = hidden idx, coalesced L1-hit reads.
    // alpha==0 rows (incl. masked tokens) skipped; preserves t-order of
    // nonzero terms so fp32 accumulation matches the reference-ordered sum
    // within normal fp tolerance.
    float acc = 0.f;
    for (int t = 0; t < T_; t++) {
        float av = alpha_s[t];
        if (av != 0.f)
            acc += av * emb[(long)xs_s[t] * H_ + tid];
    }
    g_sen[(b * S_ + s) * DIN + tid] = acc;

    // feat_part: sum of valid token features
    if (tid < F_) {
        float fa = 0.f;
        const float* fp = xfeat + base * F_ + tid;
        #pragma unroll 4
        for (int t = 0; t < T_; t++)
            if (score_s[t] > -1e29f) fa += fp[t * F_];
        g_sen[(b * S_ + s) * DIN + H_ + tid] = fa;
    }
}

// ---------------- XW GEMM via tf32 tensor cores, 64-row tiles + lens skip ---
#define PA 36
#define PW 36
__global__ void __launch_bounds__(256) xw_gemm_kernel(
    const float* __restrict__ wf, const float* __restrict__ wb,
    const float* __restrict__ bih_f, const float* __restrict__ bhh_f,
    const float* __restrict__ bih_b, const float* __restrict__ bhh_b,
    const int* __restrict__ lens) {
    int m0 = blockIdx.x * 64;
    {
        bool live = false;
        int b0 = m0 / S_, b1 = (m0 + 63) / S_;
        for (int b = b0; b <= b1 && b < B_; b++) {
            int glen = lens[(b >> 2) << 2];          // group max (sorted desc)
            int row_lo = b * S_;
            int s_start = (m0 > row_lo) ? (m0 - row_lo) : 0;
            if (row_lo < m0 + 64 && s_start < glen) { live = true; break; }
        }
        if (!live) return;
    }
    __shared__ uint32_t As[64 * PA];
    __shared__ uint32_t Ws[128 * PW];
    int dir = blockIdx.z;
    const float* W  = dir ? wb : wf;
    const float* b1p = dir ? bih_b : bih_f;
    const float* b2p = dir ? bhh_b : bhh_f;
    int n0 = blockIdx.y * 128;
    int tid = threadIdx.x, lane = tid & 31, warp = tid >> 5;
    int wm = warp & 1, wn = warp >> 1;
    int g = lane >> 2, tq = lane & 3;

    float acc[2][4][4];
    #pragma unroll
    for (int mi = 0; mi < 2; mi++)
        #pragma unroll
        for (int ni = 0; ni < 4; ni++)
            #pragma unroll
            for (int c = 0; c < 4; c++) acc[mi][ni][c] = 0.f;

    for (int kt = 0; kt < DIN; kt += 32) {
        #pragma unroll
        for (int l = 0; l < 2; l++) {
            int i = tid + l * 256;
            int r = i >> 3, c4 = (i & 7) * 4;
            float4 v = *(const float4*)(g_sen + (long)(m0 + r) * DIN + kt + c4);
            uint32_t* d = As + r * PA + c4;
            d[0] = to_tf32(v.x); d[1] = to_tf32(v.y);
            d[2] = to_tf32(v.z); d[3] = to_tf32(v.w);
        }
        #pragma unroll
        for (int l = 0; l < 4; l++) {
            int i = tid + l * 256;
            int r = i >> 3, c4 = (i & 7) * 4;
            float4 v = *(const float4*)(W + (long)(n0 + r) * DIN + kt + c4);
            uint32_t* d = Ws + r * PW + c4;
            d[0] = to_tf32(v.x); d[1] = to_tf32(v.y);
            d[2] = to_tf32(v.z); d[3] = to_tf32(v.w);
        }
        __syncthreads();

        #pragma unroll
        for (int ks = 0; ks < 4; ks++) {
            int kb = ks * 8;
            uint32_t a[2][4];
            #pragma unroll
            for (int mi = 0; mi < 2; mi++) {
                int row = wm * 32 + mi * 16 + g;
                a[mi][0] = As[row * PA + kb + tq];
                a[mi][1] = As[(row + 8) * PA + kb + tq];
                a[mi][2] = As[row * PA + kb + tq + 4];
                a[mi][3] = As[(row + 8) * PA + kb + tq + 4];
            }
            uint32_t bfr[4][2];
            #pragma unroll
            for (int ni = 0; ni < 4; ni++) {
                int col = wn * 32 + ni * 8 + g;
                bfr[ni][0] = Ws[col * PW + kb + tq];
                bfr[ni][1] = Ws[col * PW + kb + tq + 4];
            }
            #pragma unroll
            for (int mi = 0; mi < 2; mi++)
                #pragma unroll
                for (int ni = 0; ni < 4; ni++) {
                    float* c = acc[mi][ni];
                    asm("mma.sync.aligned.m16n8k8.row.col.f32.tf32.tf32.f32 "
                        "{%0,%1,%2,%3}, {%4,%5,%6,%7}, {%8,%9}, {%0,%1,%2,%3};"
                        : "+f"(c[0]), "+f"(c[1]), "+f"(c[2]), "+f"(c[3])
                        : "r"(a[mi][0]), "r"(a[mi][1]), "r"(a[mi][2]), "r"(a[mi][3]),
                          "r"(bfr[ni][0]), "r"(bfr[ni][1]));
                }
        }
        __syncthreads();
    }

    float* C = g_XW[dir];
    #pragma unroll
    for (int ni = 0; ni < 4; ni++) {
        int col = n0 + wn * 32 + ni * 8 + 2 * tq;
        float bb0 = b1p[col] + b2p[col];
        float bb1 = b1p[col + 1] + b2p[col + 1];
        #pragma unroll
        for (int mi = 0; mi < 2; mi++) {
            int row = m0 + wm * 32 + mi * 16 + g;
            *(float2*)(C + (long)row * GH + col) =
                make_float2(acc[mi][ni][0] + bb0, acc[mi][ni][1] + bb1);
            *(float2*)(C + (long)(row + 8) * GH + col) =
                make_float2(acc[mi][ni][2] + bb0, acc[mi][ni][3] + bb1);
        }
    }
}

// ---------------- clustered bidirectional LSTM: split lo/hi h barriers -----
__global__ void __launch_bounds__(512, 1) __cluster_dims__(CLUSTER, 1, 1)
lstm_kernel(const float* __restrict__ whh_f, const float* __restrict__ whh_b,
            const int* __restrict__ lens) {
    __shared__ __align__(16) float h_s[2 * 1024];     // [p][b:4][k:256]
    __shared__ __align__(16) float g_part[4 * 512];   // [wks][gr:128][b:4]
    __shared__ __align__(8)  ull  mbar[4];            // [buf][half]

    int dir = blockIdx.x >> 6;
    int bg  = (blockIdx.x >> 3) & 7;
    int rank; asm("mov.u32 %0, %%cluster_ctarank;" : "=r"(rank));
    int tid = threadIdx.x, lane = tid & 31, warp = tid >> 5;
    int wks = warp & 3, gate = warp >> 2;
    int kk = lane >> 4, lr = lane & 15;
    const float* whh = dir ? whh_b : whh_f;

    int gu0 = 32 * rank + 2 * lr;
    int kbase = 64 * wks + 32 * kk;
    ull wp0[16], wp1[16];
    {
        const ulonglong2* w0p = (const ulonglong2*)(whh + (long)(gate * H_ + gu0) * H_ + kbase);
        const ulonglong2* w1p = (const ulonglong2*)(whh + (long)(gate * H_ + gu0 + 1) * H_ + kbase);
        #pragma unroll
        for (int q = 0; q < 8; q++) {
            ulonglong2 v0 = w0p[q], v1 = w1p[q];
            wp0[2*q] = v0.x; wp0[2*q+1] = v0.y;
            wp1[2*q] = v1.x; wp1[2*q+1] = v1.y;
        }
    }
    for (int i = tid; i < 2048; i += 512) h_s[i] = 0.f;

    uint32_t hs_base = smem_u32(h_s);
    uint32_t mbd[4];
    #pragma unroll
    for (int i = 0; i < 4; i++) mbd[i] = smem_u32(&mbar[i]) - hs_base;
    if (tid == 0) {
        #pragma unroll
        for (int i = 0; i < 4; i++) mbar_init(hs_base + mbd[i], 1);
    }

    int e_u = tid >> 2, e_b = tid & 3;           // epilogue identity (tid<128)
    int e_gu = 32 * rank + e_u;
    int e_len = lens[bg * 4 + e_b];
    int len_grp = lens[bg * 4];
    float c_reg = 0.f;
    const float* XWd = g_XW[dir];

    uint32_t peer_base[CLUSTER];
    #pragma unroll
    for (int prr = 0; prr < CLUSTER; prr++) peer_base[prr] = mapa_u32(hs_base, prr);
    int rot = (tid >> 2) & 7;

    int myhalf = (wks < 2) ? 0 : 1;
    uint32_t mbd_my[2]  = { mbd[0 * 2 + myhalf],      mbd[1 * 2 + myhalf] };
    int rh = rank >> 2;
    uint32_t mbd_st[2]  = { mbd[0 * 2 + rh],          mbd[1 * 2 + rh] };

    CLUSTER_SYNC();

    int t0    = dir ? (S_ - len_grp) : 0;
    int t_end = dir ? S_ : len_grp;
    uint32_t ph[2] = {0, 0};

    float xw[4] = {0.f, 0.f, 0.f, 0.f};
    if (tid < 128) {
        int s0 = dir ? (len_grp - 1) : 0;
        long xb = ((long)(bg * 4 + e_b) * S_ + s0) * GH + e_gu;
        #pragma unroll
        for (int g = 0; g < 4; g++) xw[g] = XWd[xb + g * H_];
    }

    for (int t = t0; t < t_end; t++) {
        int s = dir ? (S_ - 1 - t) : t;
        int p = t & 1;
        int q = p ^ 1;
        if (tid == 0) {
            mbar_expect_tx(hs_base + mbd[q * 2],     2048);
            mbar_expect_tx(hs_base + mbd[q * 2 + 1], 2048);
        }
        const float* hb = h_s + p * 1024 + kbase;

        ull a00=0, a01=0, a02=0, a03=0;
        ull a10=0, a11=0, a12=0, a13=0;
        #pragma unroll
        for (int i = 0; i < 8; i++) {
            ulonglong2 h0 = *(const ulonglong2*)(hb + 4*i);
            ulonglong2 h1 = *(const ulonglong2*)(hb + 256 + 4*i);
            ulonglong2 h2 = *(const ulonglong2*)(hb + 512 + 4*i);
            ulonglong2 h3 = *(const ulonglong2*)(hb + 768 + 4*i);
            ull wa = wp0[2*i], wb = wp0[2*i+1];
            ull wc = wp1[2*i], wd = wp1[2*i+1];
            a00 = fma2(wa, h0.x, a00); a00 = fma2(wb, h0.y, a00);
            a01 = fma2(wa, h1.x, a01); a01 = fma2(wb, h1.y, a01);
            a02 = fma2(wa, h2.x, a02); a02 = fma2(wb, h2.y, a02);
            a03 = fma2(wa, h3.x, a03); a03 = fma2(wb, h3.y, a03);
            a10 = fma2(wc, h0.x, a10); a10 = fma2(wd, h0.y, a10);
            a11 = fma2(wc, h1.x, a11); a11 = fma2(wd, h1.y, a11);
            a12 = fma2(wc, h2.x, a12); a12 = fma2(wd, h2.y, a12);
            a13 = fma2(wc, h3.x, a13); a13 = fma2(wd, h3.y, a13);
        }
        float l0, l1, s00, s01, s02, s03, s10, s11, s12, s13;
        unpackf2(a00, l0, l1); s00 = l0 + l1;
        unpackf2(a01, l0, l1); s01 = l0 + l1;
        unpackf2(a02, l0, l1); s02 = l0 + l1;
        unpackf2(a03, l0, l1); s03 = l0 + l1;
        unpackf2(a10, l0, l1); s10 = l0 + l1;
        unpackf2(a11, l0, l1); s11 = l0 + l1;
        unpackf2(a12, l0, l1); s12 = l0 + l1;
        unpackf2(a13, l0, l1); s13 = l0 + l1;
        ull r00 = packf2(s00, s01), r01 = packf2(s02, s03);
        ull r10 = packf2(s10, s11), r11 = packf2(s12, s13);
        r00 = addf2(r00, __shfl_xor_sync(0xffffffffu, r00, 16));
        r01 = addf2(r01, __shfl_xor_sync(0xffffffffu, r01, 16));
        r10 = addf2(r10, __shfl_xor_sync(0xffffffffu, r10, 16));
        r11 = addf2(r11, __shfl_xor_sync(0xffffffffu, r11, 16));
        if (kk == 0) {
            int gr0 = gate * 32 + 2 * lr;
            ull* gp = (ull*)(g_part + wks * 512 + gr0 * 4);
            gp[0] = r00; gp[1] = r01;
            gp[2] = r10; gp[3] = r11;
        }
        __syncthreads();

        if (tid < 128) {
            float gv[4];
            #pragma unroll
            for (int g = 0; g < 4; g++) {
                float sum = xw[g];
                int gi = (g * 32 + e_u) * 4 + e_b;
                #pragma unroll
                for (int ks = 0; ks < 4; ks++) sum += g_part[ks * 512 + gi];
                gv[g] = sum;
            }
            float c2 = hsig(gv[1]) * c_reg + hsig(gv[0]) * htanh(gv[2]);
            float h2 = hsig(gv[3]) * htanh(c2);
            bool upd = (s < e_len);
            float hn;
            if (upd) { c_reg = c2; hn = h2; }
            else     { hn = h_s[p * 1024 + e_b * 256 + e_gu]; }
            float q0 = hn;
            float q1 = __shfl_sync(0xffffffffu, hn, lane + 4);
            float q2 = __shfl_sync(0xffffffffu, hn, lane + 8);
            float q3 = __shfl_sync(0xffffffffu, hn, lane + 12);
            if ((e_u & 3) == 0) {
                uint32_t off = (uint32_t)((q * 1024 + e_b * 256 + e_gu) * 4);
                uint32_t mst = mbd_st[q];
                #pragma unroll
                for (int i = 0; i < CLUSTER; i++) {
                    int prr = (rot + i) & 7;
                    st_async_v4(peer_base[prr] + off, q0, q1, q2, q3,
                                peer_base[prr] + mst);
                }
            }
        }
        if (tid < 128 && t + 1 < t_end) {
            int sn = dir ? (S_ - 2 - t) : (t + 1);
            long xb = ((long)(bg * 4 + e_b) * S_ + sn) * GH + e_gu;
            #pragma unroll
            for (int g = 0; g < 4; g++) xw[g] = XWd[xb + g * H_];
        }
        mbar_wait(hs_base + mbd_my[q], ph[q]);
        ph[q] ^= 1;
    }

    __syncthreads();
    {
        int qf = ((t_end - 1) & 1) ^ 1;
        if (tid < 128)
            g_hfinal[dir][bg * 4 + e_b][e_gu] = h_s[qf * 1024 + e_b * 256 + e_gu];
    }

    CLUSTER_SYNC();
}

// ---------------- FC + BN(batch axis) + relu + log_softmax(batch axis) ----
__global__ void final_kernel(const float* __restrict__ fc_w, const float* __restrict__ fc_b,
                             const float* __restrict__ gamma, const float* __restrict__ beta,
                             float* __restrict__ out) {
    __shared__ float wsh[2 * H_];
    __shared__ float lg[B_];
    int j = blockIdx.x;
    int tid = threadIdx.x, warp = tid >> 5, lane = tid & 31;
    for (int i = tid; i < 2 * H_; i += 256) wsh[i] = fc_w[j * 2 * H_ + i];
    __syncthreads();

    #pragma unroll
    for (int ii = 0; ii < 4; ii++) {
        int i = warp * 4 + ii;
        int dirc = i >> 4;
        int bb = (i & 15) * 2;
        const float* h0 = g_hfinal[dirc][bb];
        const float* h1 = g_hfinal[dirc][bb + 1];
        float p = 0.f;
        for (int k = lane; k < H_; k += 32) p += h0[k] * wsh[k] + h1[k] * wsh[H_ + k];
        #pragma unroll
        for (int o = 16; o; o >>= 1) p += __shfl_xor_sync(0xffffffffu, p, o);
        if (lane == 0) lg[i] = p + fc_b[j];
    }
    __syncthreads();

    if (warp == 0) {
        float v = lg[lane];
        float sum = v;
        #pragma unroll
        for (int o = 16; o; o >>= 1) sum += __shfl_xor_sync(0xffffffffu, sum, o);
        float mu = sum * (1.f / 32.f);
        float d = v - mu;
        float vs = d * d;
        #pragma unroll
        for (int o = 16; o; o >>= 1) vs += __shfl_xor_sync(0xffffffffu, vs, o);
        float var = vs * (1.f / 32.f);
        float y = gamma[j] * d * rsqrtf(var + 1e-5f) + beta[j];
        y = fmaxf(y, 0.f);
        float mx = y;
        #pragma unroll
        for (int o = 16; o; o >>= 1) mx = fmaxf(mx, __shfl_xor_sync(0xffffffffu, mx, o));
        float ev = expf(y - mx);
        float se = ev;
        #pragma unroll
        for (int o = 16; o; o >>= 1) se += __shfl_xor_sync(0xffffffffu, se, o);
        out[lane * OUTD + j] = y - mx - logf(se);
    }
}

// ---------------- launch ----------------
extern "C" void kernel_launch(void* const* d_in, const int* in_sizes, int n_in,
                              void* d_out, int out_size) {
    const int*           x      = (const int*)d_in[0];
    const unsigned char* xmask  = (const unsigned char*)d_in[1];
    const float*         xfeat  = (const float*)d_in[2];
    const int*           lens   = (const int*)d_in[3];
    const float* emb    = (const float*)d_in[6];
    const float* attn_w = (const float*)d_in[7];
    const float* attn_b = (const float*)d_in[8];
    const float* wih_f  = (const float*)d_in[9];
    const float* whh_f  = (const float*)d_in[10];
    const float* bih_f  = (const float*)d_in[11];
    const float* bhh_f  = (const float*)d_in[12];
    const float* wih_b  = (const float*)d_in[13];
    const float* whh_b  = (const float*)d_in[14];
    const float* bih_b  = (const float*)d_in[15];
    const float* bhh_b  = (const float*)d_in[16];
    const float* fc_w   = (const float*)d_in[17];
    const float* fc_b   = (const float*)d_in[18];
    const float* bn_g   = (const float*)d_in[19];
    const float* bn_b   = (const float*)d_in[20];

    detect_mask_kernel<<<1, 256>>>((const uint4*)xmask, (B_ * S_ * T_) / 16);
    stage1_kernel<<<B_ * S_, 256>>>(x, xmask, xfeat, emb, attn_w, attn_b, lens);
    xw_gemm_kernel<<<dim3(1280 / 64, GH / 128, 2), 256>>>(wih_f, wih_b, bih_f, bhh_f,
                                                          bih_b, bhh_b, lens);
    lstm_kernel<<<128, 512>>>(whh_f, whh_b, lens);
    final_kernel<<<OUTD, 256>>>(fc_w, fc_b, bn_g, bn_b, (float*)d_out);
}

// round 15
// speedup vs baseline: 1.0991x; 1.0159x over previous
#include <cuda_runtime.h>
#include <math.h>
#include <stdint.h>

#define S_  40
#define B_  32
#define T_  60
#define H_  256
#define F_  64
#define DIN 320
#define OUTD 128
#define GH  1024   // 4*H
#define CLUSTER 8

typedef unsigned long long ull;

// ---------------- device scratch ----------------
__device__ float g_sen[B_ * S_ * DIN];          // sen[b][s][0:320]
__device__ float g_XW[2][B_ * S_ * GH];         // [dir][b*S+s][1024]
__device__ float g_hfinal[2][B_][H_];
__device__ int g_mask_u8;

// ---------------- helpers ----------------
__device__ __forceinline__ ull packf2(float a, float b) {
    ull r; asm("mov.b64 %0, {%1,%2};" : "=l"(r) : "f"(a), "f"(b)); return r;
}
__device__ __forceinline__ ull fma2(ull a, ull b, ull c) {
    ull d; asm("fma.rn.f32x2 %0, %1, %2, %3;" : "=l"(d) : "l"(a), "l"(b), "l"(c)); return d;
}
__device__ __forceinline__ ull addf2(ull a, ull b) {
    ull d; asm("add.rn.f32x2 %0, %1, %2;" : "=l"(d) : "l"(a), "l"(b)); return d;
}
__device__ __forceinline__ void unpackf2(ull v, float& lo, float& hi) {
    asm("mov.b64 {%0,%1}, %2;" : "=f"(lo), "=f"(hi) : "l"(v));
}
__device__ __forceinline__ uint32_t smem_u32(const void* p) {
    uint32_t a;
    asm("{ .reg .u64 t; cvta.to.shared.u64 t, %1; cvt.u32.u64 %0, t; }" : "=r"(a) : "l"(p));
    return a;
}
__device__ __forceinline__ uint32_t mapa_u32(uint32_t saddr, int rank) {
    uint32_t r;
    asm("mapa.shared::cluster.u32 %0, %1, %2;" : "=r"(r) : "r"(saddr), "r"(rank));
    return r;
}
__device__ __forceinline__ void st_async_v4(uint32_t daddr, float a, float b, float c, float d,
                                            uint32_t mbar) {
    asm volatile(
        "st.async.weak.shared::cluster.mbarrier::complete_tx::bytes.v4.f32 "
        "[%0], {%1,%2,%3,%4}, [%5];"
        :: "r"(daddr), "f"(a), "f"(b), "f"(c), "f"(d), "r"(mbar) : "memory");
}
__device__ __forceinline__ void mbar_init(uint32_t mbar, uint32_t cnt) {
    asm volatile("mbarrier.init.shared.b64 [%0], %1;" :: "r"(mbar), "r"(cnt) : "memory");
}
__device__ __forceinline__ void mbar_expect_tx(uint32_t mbar, uint32_t bytes) {
    asm volatile("mbarrier.arrive.expect_tx.shared.b64 _, [%0], %1;"
                 :: "r"(mbar), "r"(bytes) : "memory");
}
__device__ __forceinline__ void mbar_wait(uint32_t mbar, uint32_t parity) {
    asm volatile(
        "{\n\t.reg .pred P;\n\t"
        "WAIT_%=:\n\t"
        "mbarrier.try_wait.parity.acquire.cluster.shared::cta.b64 P, [%0], %1;\n\t"
        "@!P bra WAIT_%=;\n\t}"
        :: "r"(mbar), "r"(parity) : "memory");
}
__device__ __forceinline__ void cp16(uint32_t smem, const void* g) {
    asm volatile("cp.async.ca.shared.global [%0], [%1], 16;" :: "r"(smem), "l"(g) : "memory");
}
#define CP_COMMIT() asm volatile("cp.async.commit_group;" ::: "memory")
#define CLUSTER_ARRIVE() asm volatile("barrier.cluster.arrive.aligned;" ::: "memory")
#define CLUSTER_WAIT()   asm volatile("barrier.cluster.wait.aligned;"   ::: "memory")
#define CLUSTER_SYNC() do { CLUSTER_ARRIVE(); CLUSTER_WAIT(); } while (0)

__device__ __forceinline__ float htanh(float x) {
    float y; asm("tanh.approx.f32 %0, %1;" : "=f"(y) : "f"(x)); return y;
}
__device__ __forceinline__ float hsig(float x) {
    return 0.5f * htanh(0.5f * x) + 0.5f;
}

// ---------------- mask dtype detection (multi-CTA, idempotent) -------------
__global__ void detect_mask_kernel(const uint4* __restrict__ m, int nwords4) {
    int found = 0;
    for (int i = blockIdx.x * blockDim.x + threadIdx.x; i < nwords4;
         i += gridDim.x * blockDim.x) {
        uint4 v = m[i];
        if ((v.x | v.y | v.z | v.w) & 0xFFFFFF00u) { found = 1; break; }
    }
    if (__syncthreads_or(found)) {
        if (threadIdx.x == 0) g_mask_u8 = 1;   // idempotent across graph replays
    }
}

// ---------------- stage 1: attention pooling, L1-resident two-pass ----------
__global__ void __launch_bounds__(256) stage1_kernel(
    const int* __restrict__ x,
    const unsigned char* __restrict__ xmask,
    const float* __restrict__ xfeat,
    const float* __restrict__ emb,
    const float* __restrict__ attn_w,
    const float* __restrict__ attn_b,
    const int* __restrict__ lens) {
    __shared__ float score_s[64];
    __shared__ float alpha_s[64];
    __shared__ int   xs_s[64];

    int bs = blockIdx.x;
    int b = bs / S_, s = bs % S_;
    if (s >= lens[(b >> 2) << 2]) return;   // dead row, never consumed
    int tid = threadIdx.x, warp = tid >> 5, lane = tid & 31;
    int u8 = g_mask_u8;
    long base = (long)(b * S_ + s) * T_;
    float ab = attn_b[0];

    const float4* aw = (const float4*)attn_w;
    float4 w0 = aw[lane], w1 = aw[lane + 32];
    for (int t = warp; t < T_; t += 8) {
        int xi = x[base + t];
        long mi = base + t;
        unsigned char mv = u8 ? xmask[mi] : xmask[mi * 4];
        int valid = (mv == 0);
        float p = 0.f;
        if (valid) {
            const float4* er = (const float4*)(emb + (long)xi * H_);
            float4 v0 = er[lane], v1 = er[lane + 32];
            p = v0.x*w0.x + v0.y*w0.y + v0.z*w0.z + v0.w*w0.w
              + v1.x*w1.x + v1.y*w1.y + v1.z*w1.z + v1.w*w1.w;
        }
        #pragma unroll
        for (int o = 16; o; o >>= 1) p += __shfl_xor_sync(0xffffffffu, p, o);
        if (lane == 0) {
            score_s[t] = valid ? (p + ab) : -1e30f;
            xs_s[t] = xi;
        }
    }
    __syncthreads();

    if (warp == 0) {
        float s0 = (lane < T_)      ? score_s[lane]      : -1e30f;
        float s1 = (lane + 32 < T_) ? score_s[lane + 32] : -1e30f;
        float mx = fmaxf(s0, s1);
        #pragma unroll
        for (int o = 16; o; o >>= 1) mx = fmaxf(mx, __shfl_xor_sync(0xffffffffu, mx, o));
        float e0 = (s0 > -1e29f) ? expf(s0 - mx) : 0.f;
        float e1 = (s1 > -1e29f) ? expf(s1 - mx) : 0.f;
        float sum = e0 + e1;
        #pragma unroll
        for (int o = 16; o; o >>= 1) sum += __shfl_xor_sync(0xffffffffu, sum, o);
        float inv = (mx > -1e29f) ? (1.f / sum) : 0.f;
        if (lane < T_)      alpha_s[lane]      = e0 * inv;
        if (lane + 32 < T_) alpha_s[lane + 32] = e1 * inv;
    }
    __syncthreads();

    float acc = 0.f;
    for (int t = 0; t < T_; t++) {
        float av = alpha_s[t];
        if (av != 0.f)
            acc += av * emb[(long)xs_s[t] * H_ + tid];
    }
    g_sen[(b * S_ + s) * DIN + tid] = acc;

    if (tid < F_) {
        float fa = 0.f;
        const float* fp = xfeat + base * F_ + tid;
        #pragma unroll 4
        for (int t = 0; t < T_; t++)
            if (score_s[t] > -1e29f) fa += fp[t * F_];
        g_sen[(b * S_ + s) * DIN + H_ + tid] = fa;
    }
}

// ---------------- XW GEMM: tf32 mma + cp.async double-buffered pipeline -----
// 64x128 tiles, lens skip. Raw fp32 bits fed to mma (HW truncates to tf32).
#define PA 36
#define PW 36
#define GEMM_SMEM ((2 * (64 * PA + 128 * PW)) * 4)

__global__ void __launch_bounds__(256) xw_gemm_kernel(
    const float* __restrict__ wf, const float* __restrict__ wb,
    const float* __restrict__ bih_f, const float* __restrict__ bhh_f,
    const float* __restrict__ bih_b, const float* __restrict__ bhh_b,
    const int* __restrict__ lens) {
    int m0 = blockIdx.x * 64;
    {
        bool live = false;
        int b0 = m0 / S_, b1 = (m0 + 63) / S_;
        for (int b = b0; b <= b1 && b < B_; b++) {
            int glen = lens[(b >> 2) << 2];
            int row_lo = b * S_;
            int s_start = (m0 > row_lo) ? (m0 - row_lo) : 0;
            if (row_lo < m0 + 64 && s_start < glen) { live = true; break; }
        }
        if (!live) return;
    }
    extern __shared__ float gsm[];
    float* As = gsm;                      // [2][64*PA]
    float* Ws = gsm + 2 * 64 * PA;        // [2][128*PW]
    int dir = blockIdx.z;
    const float* W  = dir ? wb : wf;
    const float* b1p = dir ? bih_b : bih_f;
    const float* b2p = dir ? bhh_b : bhh_f;
    int n0 = blockIdx.y * 128;
    int tid = threadIdx.x, lane = tid & 31, warp = tid >> 5;
    int wm = warp & 1, wn = warp >> 1;
    int g = lane >> 2, tq = lane & 3;
    const float* Ag = g_sen + (long)m0 * DIN;
    const float* Wg = W + (long)n0 * DIN;

#define STAGE(buf, kt) do {                                                   \
        _Pragma("unroll")                                                     \
        for (int l = 0; l < 2; l++) {                                         \
            int idx = tid + l * 256; int r = idx >> 3, c4 = (idx & 7) * 4;    \
            cp16(smem_u32(As + (buf) * 64 * PA + r * PA + c4),                \
                 Ag + (long)r * DIN + (kt) + c4);                             \
        }                                                                     \
        _Pragma("unroll")                                                     \
        for (int l = 0; l < 4; l++) {                                         \
            int idx = tid + l * 256; int r = idx >> 3, c4 = (idx & 7) * 4;    \
            cp16(smem_u32(Ws + (buf) * 128 * PW + r * PW + c4),               \
                 Wg + (long)r * DIN + (kt) + c4);                             \
        }                                                                     \
        CP_COMMIT();                                                          \
    } while (0)

    float acc[2][4][4];
    #pragma unroll
    for (int mi = 0; mi < 2; mi++)
        #pragma unroll
        for (int ni = 0; ni < 4; ni++)
            #pragma unroll
            for (int c = 0; c < 4; c++) acc[mi][ni][c] = 0.f;

    STAGE(0, 0);
    #pragma unroll 1
    for (int it = 0; it < 10; it++) {
        if (it < 9) {
            STAGE((it + 1) & 1, (it + 1) * 32);
            asm volatile("cp.async.wait_group 1;" ::: "memory");
        } else {
            asm volatile("cp.async.wait_group 0;" ::: "memory");
        }
        __syncthreads();
        const uint32_t* Ab = (const uint32_t*)(As + (it & 1) * 64 * PA);
        const uint32_t* Wb = (const uint32_t*)(Ws + (it & 1) * 128 * PW);

        #pragma unroll
        for (int ks = 0; ks < 4; ks++) {
            int kb = ks * 8;
            uint32_t a[2][4];
            #pragma unroll
            for (int mi = 0; mi < 2; mi++) {
                int row = wm * 32 + mi * 16 + g;
                a[mi][0] = Ab[row * PA + kb + tq];
                a[mi][1] = Ab[(row + 8) * PA + kb + tq];
                a[mi][2] = Ab[row * PA + kb + tq + 4];
                a[mi][3] = Ab[(row + 8) * PA + kb + tq + 4];
            }
            uint32_t bfr[4][2];
            #pragma unroll
            for (int ni = 0; ni < 4; ni++) {
                int col = wn * 32 + ni * 8 + g;
                bfr[ni][0] = Wb[col * PW + kb + tq];
                bfr[ni][1] = Wb[col * PW + kb + tq + 4];
            }
            #pragma unroll
            for (int mi = 0; mi < 2; mi++)
                #pragma unroll
                for (int ni = 0; ni < 4; ni++) {
                    float* c = acc[mi][ni];
                    asm("mma.sync.aligned.m16n8k8.row.col.f32.tf32.tf32.f32 "
                        "{%0,%1,%2,%3}, {%4,%5,%6,%7}, {%8,%9}, {%0,%1,%2,%3};"
                        : "+f"(c[0]), "+f"(c[1]), "+f"(c[2]), "+f"(c[3])
                        : "r"(a[mi][0]), "r"(a[mi][1]), "r"(a[mi][2]), "r"(a[mi][3]),
                          "r"(bfr[ni][0]), "r"(bfr[ni][1]));
                }
        }
        __syncthreads();
    }
#undef STAGE

    float* C = g_XW[dir];
    #pragma unroll
    for (int ni = 0; ni < 4; ni++) {
        int col = n0 + wn * 32 + ni * 8 + 2 * tq;
        float bb0 = b1p[col] + b2p[col];
        float bb1 = b1p[col + 1] + b2p[col + 1];
        #pragma unroll
        for (int mi = 0; mi < 2; mi++) {
            int row = m0 + wm * 32 + mi * 16 + g;
            *(float2*)(C + (long)row * GH + col) =
                make_float2(acc[mi][ni][0] + bb0, acc[mi][ni][1] + bb1);
            *(float2*)(C + (long)(row + 8) * GH + col) =
                make_float2(acc[mi][ni][2] + bb0, acc[mi][ni][3] + bb1);
        }
    }
}

// ---------------- clustered bidirectional LSTM: split lo/hi h barriers -----
__global__ void __launch_bounds__(512, 1) __cluster_dims__(CLUSTER, 1, 1)
lstm_kernel(const float* __restrict__ whh_f, const float* __restrict__ whh_b,
            const int* __restrict__ lens) {
    __shared__ __align__(16) float h_s[2 * 1024];     // [p][b:4][k:256]
    __shared__ __align__(16) float g_part[4 * 512];   // [wks][gr:128][b:4]
    __shared__ __align__(8)  ull  mbar[4];            // [buf][half]

    int dir = blockIdx.x >> 6;
    int bg  = (blockIdx.x >> 3) & 7;
    int rank; asm("mov.u32 %0, %%cluster_ctarank;" : "=r"(rank));
    int tid = threadIdx.x, lane = tid & 31, warp = tid >> 5;
    int wks = warp & 3, gate = warp >> 2;
    int kk = lane >> 4, lr = lane & 15;
    const float* whh = dir ? whh_b : whh_f;

    int gu0 = 32 * rank + 2 * lr;
    int kbase = 64 * wks + 32 * kk;
    ull wp0[16], wp1[16];
    {
        const ulonglong2* w0p = (const ulonglong2*)(whh + (long)(gate * H_ + gu0) * H_ + kbase);
        const ulonglong2* w1p = (const ulonglong2*)(whh + (long)(gate * H_ + gu0 + 1) * H_ + kbase);
        #pragma unroll
        for (int q = 0; q < 8; q++) {
            ulonglong2 v0 = w0p[q], v1 = w1p[q];
            wp0[2*q] = v0.x; wp0[2*q+1] = v0.y;
            wp1[2*q] = v1.x; wp1[2*q+1] = v1.y;
        }
    }
    for (int i = tid; i < 2048; i += 512) h_s[i] = 0.f;

    uint32_t hs_base = smem_u32(h_s);
    uint32_t mbd[4];
    #pragma unroll
    for (int i = 0; i < 4; i++) mbd[i] = smem_u32(&mbar[i]) - hs_base;
    if (tid == 0) {
        #pragma unroll
        for (int i = 0; i < 4; i++) mbar_init(hs_base + mbd[i], 1);
    }

    int e_u = tid >> 2, e_b = tid & 3;
    int e_gu = 32 * rank + e_u;
    int e_len = lens[bg * 4 + e_b];
    int len_grp = lens[bg * 4];
    float c_reg = 0.f;
    const float* XWd = g_XW[dir];

    uint32_t peer_base[CLUSTER];
    #pragma unroll
    for (int prr = 0; prr < CLUSTER; prr++) peer_base[prr] = mapa_u32(hs_base, prr);
    int rot = (tid >> 2) & 7;

    int myhalf = (wks < 2) ? 0 : 1;
    uint32_t mbd_my[2]  = { mbd[0 * 2 + myhalf],      mbd[1 * 2 + myhalf] };
    int rh = rank >> 2;
    uint32_t mbd_st[2]  = { mbd[0 * 2 + rh],          mbd[1 * 2 + rh] };

    CLUSTER_SYNC();

    int t0    = dir ? (S_ - len_grp) : 0;
    int t_end = dir ? S_ : len_grp;
    uint32_t ph[2] = {0, 0};

    float xw[4] = {0.f, 0.f, 0.f, 0.f};
    if (tid < 128) {
        int s0 = dir ? (len_grp - 1) : 0;
        long xb = ((long)(bg * 4 + e_b) * S_ + s0) * GH + e_gu;
        #pragma unroll
        for (int g = 0; g < 4; g++) xw[g] = XWd[xb + g * H_];
    }

    for (int t = t0; t < t_end; t++) {
        int s = dir ? (S_ - 1 - t) : t;
        int p = t & 1;
        int q = p ^ 1;
        if (tid == 0) {
            mbar_expect_tx(hs_base + mbd[q * 2],     2048);
            mbar_expect_tx(hs_base + mbd[q * 2 + 1], 2048);
        }
        const float* hb = h_s + p * 1024 + kbase;

        ull a00=0, a01=0, a02=0, a03=0;
        ull a10=0, a11=0, a12=0, a13=0;
        #pragma unroll
        for (int i = 0; i < 8; i++) {
            ulonglong2 h0 = *(const ulonglong2*)(hb + 4*i);
            ulonglong2 h1 = *(const ulonglong2*)(hb + 256 + 4*i);
            ulonglong2 h2 = *(const ulonglong2*)(hb + 512 + 4*i);
            ulonglong2 h3 = *(const ulonglong2*)(hb + 768 + 4*i);
            ull wa = wp0[2*i], wb = wp0[2*i+1];
            ull wc = wp1[2*i], wd = wp1[2*i+1];
            a00 = fma2(wa, h0.x, a00); a00 = fma2(wb, h0.y, a00);
            a01 = fma2(wa, h1.x, a01); a01 = fma2(wb, h1.y, a01);
            a02 = fma2(wa, h2.x, a02); a02 = fma2(wb, h2.y, a02);
            a03 = fma2(wa, h3.x, a03); a03 = fma2(wb, h3.y, a03);
            a10 = fma2(wc, h0.x, a10); a10 = fma2(wd, h0.y, a10);
            a11 = fma2(wc, h1.x, a11); a11 = fma2(wd, h1.y, a11);
            a12 = fma2(wc, h2.x, a12); a12 = fma2(wd, h2.y, a12);
            a13 = fma2(wc, h3.x, a13); a13 = fma2(wd, h3.y, a13);
        }
        float l0, l1, s00, s01, s02, s03, s10, s11, s12, s13;
        unpackf2(a00, l0, l1); s00 = l0 + l1;
        unpackf2(a01, l0, l1); s01 = l0 + l1;
        unpackf2(a02, l0, l1); s02 = l0 + l1;
        unpackf2(a03, l0, l1); s03 = l0 + l1;
        unpackf2(a10, l0, l1); s10 = l0 + l1;
        unpackf2(a11, l0, l1); s11 = l0 + l1;
        unpackf2(a12, l0, l1); s12 = l0 + l1;
        unpackf2(a13, l0, l1); s13 = l0 + l1;
        ull r00 = packf2(s00, s01), r01 = packf2(s02, s03);
        ull r10 = packf2(s10, s11), r11 = packf2(s12, s13);
        r00 = addf2(r00, __shfl_xor_sync(0xffffffffu, r00, 16));
        r01 = addf2(r01, __shfl_xor_sync(0xffffffffu, r01, 16));
        r10 = addf2(r10, __shfl_xor_sync(0xffffffffu, r10, 16));
        r11 = addf2(r11, __shfl_xor_sync(0xffffffffu, r11, 16));
        if (kk == 0) {
            int gr0 = gate * 32 + 2 * lr;
            ull* gp = (ull*)(g_part + wks * 512 + gr0 * 4);
            gp[0] = r00; gp[1] = r01;
            gp[2] = r10; gp[3] = r11;
        }
        __syncthreads();

        if (tid < 128) {
            float gv[4];
            #pragma unroll
            for (int g = 0; g < 4; g++) {
                float sum = xw[g];
                int gi = (g * 32 + e_u) * 4 + e_b;
                #pragma unroll
                for (int ks = 0; ks < 4; ks++) sum += g_part[ks * 512 + gi];
                gv[g] = sum;
            }
            float c2 = hsig(gv[1]) * c_reg + hsig(gv[0]) * htanh(gv[2]);
            float h2 = hsig(gv[3]) * htanh(c2);
            bool upd = (s < e_len);
            float hn;
            if (upd) { c_reg = c2; hn = h2; }
            else     { hn = h_s[p * 1024 + e_b * 256 + e_gu]; }
            float q0 = hn;
            float q1 = __shfl_sync(0xffffffffu, hn, lane + 4);
            float q2 = __shfl_sync(0xffffffffu, hn, lane + 8);
            float q3 = __shfl_sync(0xffffffffu, hn, lane + 12);
            if ((e_u & 3) == 0) {
                uint32_t off = (uint32_t)((q * 1024 + e_b * 256 + e_gu) * 4);
                uint32_t mst = mbd_st[q];
                #pragma unroll
                for (int i = 0; i < CLUSTER; i++) {
                    int prr = (rot + i) & 7;
                    st_async_v4(peer_base[prr] + off, q0, q1, q2, q3,
                                peer_base[prr] + mst);
                }
            }
        }
        if (tid < 128 && t + 1 < t_end) {
            int sn = dir ? (S_ - 2 - t) : (t + 1);
            long xb = ((long)(bg * 4 + e_b) * S_ + sn) * GH + e_gu;
            #pragma unroll
            for (int g = 0; g < 4; g++) xw[g] = XWd[xb + g * H_];
        }
        mbar_wait(hs_base + mbd_my[q], ph[q]);
        ph[q] ^= 1;
    }

    __syncthreads();
    {
        int qf = ((t_end - 1) & 1) ^ 1;
        if (tid < 128)
            g_hfinal[dir][bg * 4 + e_b][e_gu] = h_s[qf * 1024 + e_b * 256 + e_gu];
    }

    CLUSTER_SYNC();
}

// ---------------- FC + BN(batch axis) + relu + log_softmax(batch axis) ----
__global__ void final_kernel(const float* __restrict__ fc_w, const float* __restrict__ fc_b,
                             const float* __restrict__ gamma, const float* __restrict__ beta,
                             float* __restrict__ out) {
    __shared__ float wsh[2 * H_];
    __shared__ float lg[B_];
    int j = blockIdx.x;
    int tid = threadIdx.x, warp = tid >> 5, lane = tid & 31;
    for (int i = tid; i < 2 * H_; i += 256) wsh[i] = fc_w[j * 2 * H_ + i];
    __syncthreads();

    #pragma unroll
    for (int ii = 0; ii < 4; ii++) {
        int i = warp * 4 + ii;
        int dirc = i >> 4;
        int bb = (i & 15) * 2;
        const float* h0 = g_hfinal[dirc][bb];
        const float* h1 = g_hfinal[dirc][bb + 1];
        float p = 0.f;
        for (int k = lane; k < H_; k += 32) p += h0[k] * wsh[k] + h1[k] * wsh[H_ + k];
        #pragma unroll
        for (int o = 16; o; o >>= 1) p += __shfl_xor_sync(0xffffffffu, p, o);
        if (lane == 0) lg[i] = p + fc_b[j];
    }
    __syncthreads();

    if (warp == 0) {
        float v = lg[lane];
        float sum = v;
        #pragma unroll
        for (int o = 16; o; o >>= 1) sum += __shfl_xor_sync(0xffffffffu, sum, o);
        float mu = sum * (1.f / 32.f);
        float d = v - mu;
        float vs = d * d;
        #pragma unroll
        for (int o = 16; o; o >>= 1) vs += __shfl_xor_sync(0xffffffffu, vs, o);
        float var = vs * (1.f / 32.f);
        float y = gamma[j] * d * rsqrtf(var + 1e-5f) + beta[j];
        y = fmaxf(y, 0.f);
        float mx = y;
        #pragma unroll
        for (int o = 16; o; o >>= 1) mx = fmaxf(mx, __shfl_xor_sync(0xffffffffu, mx, o));
        float ev = expf(y - mx);
        float se = ev;
        #pragma unroll
        for (int o = 16; o; o >>= 1) se += __shfl_xor_sync(0xffffffffu, se, o);
        out[lane * OUTD + j] = y - mx - logf(se);
    }
}

// ---------------- launch ----------------
extern "C" void kernel_launch(void* const* d_in, const int* in_sizes, int n_in,
                              void* d_out, int out_size) {
    const int*           x      = (const int*)d_in[0];
    const unsigned char* xmask  = (const unsigned char*)d_in[1];
    const float*         xfeat  = (const float*)d_in[2];
    const int*           lens   = (const int*)d_in[3];
    const float* emb    = (const float*)d_in[6];
    const float* attn_w = (const float*)d_in[7];
    const float* attn_b = (const float*)d_in[8];
    const float* wih_f  = (const float*)d_in[9];
    const float* whh_f  = (const float*)d_in[10];
    const float* bih_f  = (const float*)d_in[11];
    const float* bhh_f  = (const float*)d_in[12];
    const float* wih_b  = (const float*)d_in[13];
    const float* whh_b  = (const float*)d_in[14];
    const float* bih_b  = (const float*)d_in[15];
    const float* bhh_b  = (const float*)d_in[16];
    const float* fc_w   = (const float*)d_in[17];
    const float* fc_b   = (const float*)d_in[18];
    const float* bn_g   = (const float*)d_in[19];
    const float* bn_b   = (const float*)d_in[20];

    cudaFuncSetAttribute(xw_gemm_kernel, cudaFuncAttributeMaxDynamicSharedMemorySize,
                         GEMM_SMEM);

    detect_mask_kernel<<<64, 256>>>((const uint4*)xmask, (B_ * S_ * T_) / 16);
    stage1_kernel<<<B_ * S_, 256>>>(x, xmask, xfeat, emb, attn_w, attn_b, lens);
    xw_gemm_kernel<<<dim3(1280 / 64, GH / 128, 2), 256, GEMM_SMEM>>>(
        wih_f, wih_b, bih_f, bhh_f, bih_b, bhh_b, lens);
    lstm_kernel<<<128, 512>>>(whh_f, whh_b, lens);
    final_kernel<<<OUTD, 256>>>(fc_w, fc_b, bn_g, bn_b, (float*)d_out);
}

// round 16
// speedup vs baseline: 1.1556x; 1.0514x over previous
#include <cuda_runtime.h>
#include <math.h>
#include <stdint.h>

#define S_  40
#define B_  32
#define T_  60
#define H_  256
#define F_  64
#define DIN 320
#define OUTD 128
#define GH  1024   // 4*H
#define CLUSTER 8
#define MTILES 20

typedef unsigned long long ull;

// ---------------- device scratch ----------------
__device__ float g_sen[B_ * S_ * DIN];          // sen[b][s][0:320]
__device__ float g_XW[2][B_ * S_ * GH];         // [dir][b*S+s][1024]
__device__ float g_hfinal[2][B_][H_];
__device__ int g_mask_u8;
__device__ int g_xw_flag[2][MTILES];            // gemm->lstm readiness (reset by final)

// ---------------- helpers ----------------
__device__ __forceinline__ ull packf2(float a, float b) {
    ull r; asm("mov.b64 %0, {%1,%2};" : "=l"(r) : "f"(a), "f"(b)); return r;
}
__device__ __forceinline__ ull fma2(ull a, ull b, ull c) {
    ull d; asm("fma.rn.f32x2 %0, %1, %2, %3;" : "=l"(d) : "l"(a), "l"(b), "l"(c)); return d;
}
__device__ __forceinline__ ull addf2(ull a, ull b) {
    ull d; asm("add.rn.f32x2 %0, %1, %2;" : "=l"(d) : "l"(a), "l"(b)); return d;
}
__device__ __forceinline__ void unpackf2(ull v, float& lo, float& hi) {
    asm("mov.b64 {%0,%1}, %2;" : "=f"(lo), "=f"(hi) : "l"(v));
}
__device__ __forceinline__ uint32_t smem_u32(const void* p) {
    uint32_t a;
    asm("{ .reg .u64 t; cvta.to.shared.u64 t, %1; cvt.u32.u64 %0, t; }" : "=r"(a) : "l"(p));
    return a;
}
__device__ __forceinline__ uint32_t mapa_u32(uint32_t saddr, int rank) {
    uint32_t r;
    asm("mapa.shared::cluster.u32 %0, %1, %2;" : "=r"(r) : "r"(saddr), "r"(rank));
    return r;
}
__device__ __forceinline__ void st_async_v4(uint32_t daddr, float a, float b, float c, float d,
                                            uint32_t mbar) {
    asm volatile(
        "st.async.weak.shared::cluster.mbarrier::complete_tx::bytes.v4.f32 "
        "[%0], {%1,%2,%3,%4}, [%5];"
        :: "r"(daddr), "f"(a), "f"(b), "f"(c), "f"(d), "r"(mbar) : "memory");
}
__device__ __forceinline__ void mbar_init(uint32_t mbar, uint32_t cnt) {
    asm volatile("mbarrier.init.shared.b64 [%0], %1;" :: "r"(mbar), "r"(cnt) : "memory");
}
__device__ __forceinline__ void mbar_expect_tx(uint32_t mbar, uint32_t bytes) {
    asm volatile("mbarrier.arrive.expect_tx.shared.b64 _, [%0], %1;"
                 :: "r"(mbar), "r"(bytes) : "memory");
}
__device__ __forceinline__ void mbar_wait(uint32_t mbar, uint32_t parity) {
    asm volatile(
        "{\n\t.reg .pred P;\n\t"
        "WAIT_%=:\n\t"
        "mbarrier.try_wait.parity.acquire.cluster.shared::cta.b64 P, [%0], %1;\n\t"
        "@!P bra WAIT_%=;\n\t}"
        :: "r"(mbar), "r"(parity) : "memory");
}
__device__ __forceinline__ void cp16(uint32_t smem, const void* g) {
    asm volatile("cp.async.ca.shared.global [%0], [%1], 16;" :: "r"(smem), "l"(g) : "memory");
}
__device__ __forceinline__ int ld_acq(const int* p) {
    int v; asm volatile("ld.acquire.gpu.global.s32 %0, [%1];" : "=r"(v) : "l"(p) : "memory");
    return v;
}
#define CP_COMMIT() asm volatile("cp.async.commit_group;" ::: "memory")
#define CLUSTER_ARRIVE() asm volatile("barrier.cluster.arrive.aligned;" ::: "memory")
#define CLUSTER_WAIT()   asm volatile("barrier.cluster.wait.aligned;"   ::: "memory")
#define CLUSTER_SYNC() do { CLUSTER_ARRIVE(); CLUSTER_WAIT(); } while (0)

__device__ __forceinline__ float htanh(float x) {
    float y; asm("tanh.approx.f32 %0, %1;" : "=f"(y) : "f"(x)); return y;
}
__device__ __forceinline__ float hsig(float x) {
    return 0.5f * htanh(0.5f * x) + 0.5f;
}

// ---------------- mask dtype detection (multi-CTA, idempotent) -------------
__global__ void detect_mask_kernel(const uint4* __restrict__ m, int nwords4) {
    int found = 0;
    for (int i = blockIdx.x * blockDim.x + threadIdx.x; i < nwords4;
         i += gridDim.x * blockDim.x) {
        uint4 v = m[i];
        if ((v.x | v.y | v.z | v.w) & 0xFFFFFF00u) { found = 1; break; }
    }
    if (__syncthreads_or(found)) {
        if (threadIdx.x == 0) g_mask_u8 = 1;
    }
}

// ---------------- stage 1: attention pooling, L1-resident two-pass ----------
__global__ void __launch_bounds__(256) stage1_kernel(
    const int* __restrict__ x,
    const unsigned char* __restrict__ xmask,
    const float* __restrict__ xfeat,
    const float* __restrict__ emb,
    const float* __restrict__ attn_w,
    const float* __restrict__ attn_b,
    const int* __restrict__ lens) {
    __shared__ float score_s[64];
    __shared__ float alpha_s[64];
    __shared__ int   xs_s[64];

    int bs = blockIdx.x;
    int b = bs / S_, s = bs % S_;
    if (s >= lens[(b >> 2) << 2]) return;
    int tid = threadIdx.x, warp = tid >> 5, lane = tid & 31;
    int u8 = g_mask_u8;
    long base = (long)(b * S_ + s) * T_;
    float ab = attn_b[0];

    const float4* aw = (const float4*)attn_w;
    float4 w0 = aw[lane], w1 = aw[lane + 32];
    for (int t = warp; t < T_; t += 8) {
        int xi = x[base + t];
        long mi = base + t;
        unsigned char mv = u8 ? xmask[mi] : xmask[mi * 4];
        int valid = (mv == 0);
        float p = 0.f;
        if (valid) {
            const float4* er = (const float4*)(emb + (long)xi * H_);
            float4 v0 = er[lane], v1 = er[lane + 32];
            p = v0.x*w0.x + v0.y*w0.y + v0.z*w0.z + v0.w*w0.w
              + v1.x*w1.x + v1.y*w1.y + v1.z*w1.z + v1.w*w1.w;
        }
        #pragma unroll
        for (int o = 16; o; o >>= 1) p += __shfl_xor_sync(0xffffffffu, p, o);
        if (lane == 0) {
            score_s[t] = valid ? (p + ab) : -1e30f;
            xs_s[t] = xi;
        }
    }
    __syncthreads();

    if (warp == 0) {
        float s0 = (lane < T_)      ? score_s[lane]      : -1e30f;
        float s1 = (lane + 32 < T_) ? score_s[lane + 32] : -1e30f;
        float mx = fmaxf(s0, s1);
        #pragma unroll
        for (int o = 16; o; o >>= 1) mx = fmaxf(mx, __shfl_xor_sync(0xffffffffu, mx, o));
        float e0 = (s0 > -1e29f) ? expf(s0 - mx) : 0.f;
        float e1 = (s1 > -1e29f) ? expf(s1 - mx) : 0.f;
        float sum = e0 + e1;
        #pragma unroll
        for (int o = 16; o; o >>= 1) sum += __shfl_xor_sync(0xffffffffu, sum, o);
        float inv = (mx > -1e29f) ? (1.f / sum) : 0.f;
        if (lane < T_)      alpha_s[lane]      = e0 * inv;
        if (lane + 32 < T_) alpha_s[lane + 32] = e1 * inv;
    }
    __syncthreads();

    float acc = 0.f;
    for (int t = 0; t < T_; t++) {
        float av = alpha_s[t];
        if (av != 0.f)
            acc += av * emb[(long)xs_s[t] * H_ + tid];
    }
    g_sen[(b * S_ + s) * DIN + tid] = acc;

    if (tid < F_) {
        float fa = 0.f;
        const float* fp = xfeat + base * F_ + tid;
        #pragma unroll 4
        for (int t = 0; t < T_; t++)
            if (score_s[t] > -1e29f) fa += fp[t * F_];
        g_sen[(b * S_ + s) * DIN + H_ + tid] = fa;
    }
}

// ---------------- XW GEMM: tf32 mma + cp.async pipeline + readiness flags ---
#define PA 36
#define PW 36
#define GEMM_SMEM ((2 * (64 * PA + 128 * PW)) * 4)

__global__ void __launch_bounds__(256) xw_gemm_kernel(
    const float* __restrict__ wf, const float* __restrict__ wb,
    const float* __restrict__ bih_f, const float* __restrict__ bhh_f,
    const float* __restrict__ bih_b, const float* __restrict__ bhh_b,
    const int* __restrict__ lens) {
    cudaTriggerProgrammaticLaunchCompletion();   // let the lstm launch early
    int m0 = blockIdx.x * 64;
    {
        bool live = false;
        int b0 = m0 / S_, b1 = (m0 + 63) / S_;
        for (int b = b0; b <= b1 && b < B_; b++) {
            int glen = lens[(b >> 2) << 2];
            int row_lo = b * S_;
            int s_start = (m0 > row_lo) ? (m0 - row_lo) : 0;
            if (row_lo < m0 + 64 && s_start < glen) { live = true; break; }
        }
        if (!live) return;
    }
    extern __shared__ float gsm[];
    float* As = gsm;
    float* Ws = gsm + 2 * 64 * PA;
    int dir = blockIdx.z;
    const float* W  = dir ? wb : wf;
    const float* b1p = dir ? bih_b : bih_f;
    const float* b2p = dir ? bhh_b : bhh_f;
    int n0 = blockIdx.y * 128;
    int tid = threadIdx.x, lane = tid & 31, warp = tid >> 5;
    int wm = warp & 1, wn = warp >> 1;
    int g = lane >> 2, tq = lane & 3;
    const float* Ag = g_sen + (long)m0 * DIN;
    const float* Wg = W + (long)n0 * DIN;

#define STAGE(buf, kt) do {                                                   \
        _Pragma("unroll")                                                     \
        for (int l = 0; l < 2; l++) {                                         \
            int idx = tid + l * 256; int r = idx >> 3, c4 = (idx & 7) * 4;    \
            cp16(smem_u32(As + (buf) * 64 * PA + r * PA + c4),                \
                 Ag + (long)r * DIN + (kt) + c4);                             \
        }                                                                     \
        _Pragma("unroll")                                                     \
        for (int l = 0; l < 4; l++) {                                         \
            int idx = tid + l * 256; int r = idx >> 3, c4 = (idx & 7) * 4;    \
            cp16(smem_u32(Ws + (buf) * 128 * PW + r * PW + c4),               \
                 Wg + (long)r * DIN + (kt) + c4);                             \
        }                                                                     \
        CP_COMMIT();                                                          \
    } while (0)

    float acc[2][4][4];
    #pragma unroll
    for (int mi = 0; mi < 2; mi++)
        #pragma unroll
        for (int ni = 0; ni < 4; ni++)
            #pragma unroll
            for (int c = 0; c < 4; c++) acc[mi][ni][c] = 0.f;

    STAGE(0, 0);
    #pragma unroll 1
    for (int it = 0; it < 10; it++) {
        if (it < 9) {
            STAGE((it + 1) & 1, (it + 1) * 32);
            asm volatile("cp.async.wait_group 1;" ::: "memory");
        } else {
            asm volatile("cp.async.wait_group 0;" ::: "memory");
        }
        __syncthreads();
        const uint32_t* Ab = (const uint32_t*)(As + (it & 1) * 64 * PA);
        const uint32_t* Wb = (const uint32_t*)(Ws + (it & 1) * 128 * PW);

        #pragma unroll
        for (int ks = 0; ks < 4; ks++) {
            int kb = ks * 8;
            uint32_t a[2][4];
            #pragma unroll
            for (int mi = 0; mi < 2; mi++) {
                int row = wm * 32 + mi * 16 + g;
                a[mi][0] = Ab[row * PA + kb + tq];
                a[mi][1] = Ab[(row + 8) * PA + kb + tq];
                a[mi][2] = Ab[row * PA + kb + tq + 4];
                a[mi][3] = Ab[(row + 8) * PA + kb + tq + 4];
            }
            uint32_t bfr[4][2];
            #pragma unroll
            for (int ni = 0; ni < 4; ni++) {
                int col = wn * 32 + ni * 8 + g;
                bfr[ni][0] = Wb[col * PW + kb + tq];
                bfr[ni][1] = Wb[col * PW + kb + tq + 4];
            }
            #pragma unroll
            for (int mi = 0; mi < 2; mi++)
                #pragma unroll
                for (int ni = 0; ni < 4; ni++) {
                    float* c = acc[mi][ni];
                    asm("mma.sync.aligned.m16n8k8.row.col.f32.tf32.tf32.f32 "
                        "{%0,%1,%2,%3}, {%4,%5,%6,%7}, {%8,%9}, {%0,%1,%2,%3};"
                        : "+f"(c[0]), "+f"(c[1]), "+f"(c[2]), "+f"(c[3])
                        : "r"(a[mi][0]), "r"(a[mi][1]), "r"(a[mi][2]), "r"(a[mi][3]),
                          "r"(bfr[ni][0]), "r"(bfr[ni][1]));
                }
        }
        __syncthreads();
    }
#undef STAGE

    float* C = g_XW[dir];
    #pragma unroll
    for (int ni = 0; ni < 4; ni++) {
        int col = n0 + wn * 32 + ni * 8 + 2 * tq;
        float bb0 = b1p[col] + b2p[col];
        float bb1 = b1p[col + 1] + b2p[col + 1];
        #pragma unroll
        for (int mi = 0; mi < 2; mi++) {
            int row = m0 + wm * 32 + mi * 16 + g;
            *(float2*)(C + (long)row * GH + col) =
                make_float2(acc[mi][ni][0] + bb0, acc[mi][ni][1] + bb1);
            *(float2*)(C + (long)(row + 8) * GH + col) =
                make_float2(acc[mi][ni][2] + bb0, acc[mi][ni][3] + bb1);
        }
    }
    // release: C stores -> fence -> flag increment (8 n-tiles => flag==8)
    __threadfence();
    __syncthreads();
    if (tid == 0) atomicAdd(&g_xw_flag[dir][blockIdx.x], 1);
}

// ---------------- clustered bidirectional LSTM (PDL, flag-gated XW) --------
__global__ void __launch_bounds__(512, 1) __cluster_dims__(CLUSTER, 1, 1)
lstm_kernel(const float* __restrict__ whh_f, const float* __restrict__ whh_b,
            const int* __restrict__ lens) {
    __shared__ __align__(16) float h_s[2 * 1024];     // [p][b:4][k:256]
    __shared__ __align__(16) float g_part[4 * 512];   // [wks][gr:128][b:4]
    __shared__ __align__(8)  ull  mbar[4];            // [buf][half]

    int dir = blockIdx.x >> 6;
    int bg  = (blockIdx.x >> 3) & 7;
    int rank; asm("mov.u32 %0, %%cluster_ctarank;" : "=r"(rank));
    int tid = threadIdx.x, lane = tid & 31, warp = tid >> 5;
    int wks = warp & 3, gate = warp >> 2;
    int kk = lane >> 4, lr = lane & 15;
    const float* whh = dir ? whh_b : whh_f;

    int gu0 = 32 * rank + 2 * lr;
    int kbase = 64 * wks + 32 * kk;
    ull wp0[16], wp1[16];
    {
        const ulonglong2* w0p = (const ulonglong2*)(whh + (long)(gate * H_ + gu0) * H_ + kbase);
        const ulonglong2* w1p = (const ulonglong2*)(whh + (long)(gate * H_ + gu0 + 1) * H_ + kbase);
        #pragma unroll
        for (int q = 0; q < 8; q++) {
            ulonglong2 v0 = w0p[q], v1 = w1p[q];
            wp0[2*q] = v0.x; wp0[2*q+1] = v0.y;
            wp1[2*q] = v1.x; wp1[2*q+1] = v1.y;
        }
    }
    for (int i = tid; i < 2048; i += 512) h_s[i] = 0.f;

    uint32_t hs_base = smem_u32(h_s);
    uint32_t mbd[4];
    #pragma unroll
    for (int i = 0; i < 4; i++) mbd[i] = smem_u32(&mbar[i]) - hs_base;
    if (tid == 0) {
        #pragma unroll
        for (int i = 0; i < 4; i++) mbar_init(hs_base + mbd[i], 1);
    }

    int e_u = tid >> 2, e_b = tid & 3;
    int e_gu = 32 * rank + e_u;
    int e_len = lens[bg * 4 + e_b];
    int len_grp = lens[bg * 4];
    int e_row = (bg * 4 + e_b) * S_;
    float c_reg = 0.f;
    const float* XWd = g_XW[dir];
    const int* flags = g_xw_flag[dir];
    uint32_t done_mask = 0;

    uint32_t peer_base[CLUSTER];
    #pragma unroll
    for (int prr = 0; prr < CLUSTER; prr++) peer_base[prr] = mapa_u32(hs_base, prr);
    int rot = (tid >> 2) & 7;

    int myhalf = (wks < 2) ? 0 : 1;
    uint32_t mbd_my[2]  = { mbd[0 * 2 + myhalf],      mbd[1 * 2 + myhalf] };
    int rh = rank >> 2;
    uint32_t mbd_st[2]  = { mbd[0 * 2 + rh],          mbd[1 * 2 + rh] };

    CLUSTER_SYNC();

    int t0    = dir ? (S_ - len_grp) : 0;
    int t_end = dir ? S_ : len_grp;
    uint32_t ph[2] = {0, 0};

    for (int t = t0; t < t_end; t++) {
        int s = dir ? (S_ - 1 - t) : t;
        int p = t & 1;
        int q = p ^ 1;
        if (tid == 0) {
            mbar_expect_tx(hs_base + mbd[q * 2],     2048);
            mbar_expect_tx(hs_base + mbd[q * 2 + 1], 2048);
        }

        // XW load for THIS step, gated by tile readiness; issued before the
        // FMA loop so the LDG latency hides under compute.
        float xw[4] = {0.f, 0.f, 0.f, 0.f};
        if (tid < 128 && s < e_len) {
            int m = e_row + s;
            int tl = m >> 6;
            if (!((done_mask >> tl) & 1u)) {
                while (ld_acq(&flags[tl]) < 8) { }
                done_mask |= 1u << tl;
            }
            long xb = (long)m * GH + e_gu;
            #pragma unroll
            for (int g = 0; g < 4; g++) xw[g] = XWd[xb + g * H_];
        }

        const float* hb = h_s + p * 1024 + kbase;
        ull a00=0, a01=0, a02=0, a03=0;
        ull a10=0, a11=0, a12=0, a13=0;
        #pragma unroll
        for (int i = 0; i < 8; i++) {
            ulonglong2 h0 = *(const ulonglong2*)(hb + 4*i);
            ulonglong2 h1 = *(const ulonglong2*)(hb + 256 + 4*i);
            ulonglong2 h2 = *(const ulonglong2*)(hb + 512 + 4*i);
            ulonglong2 h3 = *(const ulonglong2*)(hb + 768 + 4*i);
            ull wa = wp0[2*i], wb = wp0[2*i+1];
            ull wc = wp1[2*i], wd = wp1[2*i+1];
            a00 = fma2(wa, h0.x, a00); a00 = fma2(wb, h0.y, a00);
            a01 = fma2(wa, h1.x, a01); a01 = fma2(wb, h1.y, a01);
            a02 = fma2(wa, h2.x, a02); a02 = fma2(wb, h2.y, a02);
            a03 = fma2(wa, h3.x, a03); a03 = fma2(wb, h3.y, a03);
            a10 = fma2(wc, h0.x, a10); a10 = fma2(wd, h0.y, a10);
            a11 = fma2(wc, h1.x, a11); a11 = fma2(wd, h1.y, a11);
            a12 = fma2(wc, h2.x, a12); a12 = fma2(wd, h2.y, a12);
            a13 = fma2(wc, h3.x, a13); a13 = fma2(wd, h3.y, a13);
        }
        float l0, l1, s00, s01, s02, s03, s10, s11, s12, s13;
        unpackf2(a00, l0, l1); s00 = l0 + l1;
        unpackf2(a01, l0, l1); s01 = l0 + l1;
        unpackf2(a02, l0, l1); s02 = l0 + l1;
        unpackf2(a03, l0, l1); s03 = l0 + l1;
        unpackf2(a10, l0, l1); s10 = l0 + l1;
        unpackf2(a11, l0, l1); s11 = l0 + l1;
        unpackf2(a12, l0, l1); s12 = l0 + l1;
        unpackf2(a13, l0, l1); s13 = l0 + l1;
        ull r00 = packf2(s00, s01), r01 = packf2(s02, s03);
        ull r10 = packf2(s10, s11), r11 = packf2(s12, s13);
        r00 = addf2(r00, __shfl_xor_sync(0xffffffffu, r00, 16));
        r01 = addf2(r01, __shfl_xor_sync(0xffffffffu, r01, 16));
        r10 = addf2(r10, __shfl_xor_sync(0xffffffffu, r10, 16));
        r11 = addf2(r11, __shfl_xor_sync(0xffffffffu, r11, 16));
        if (kk == 0) {
            int gr0 = gate * 32 + 2 * lr;
            ull* gp = (ull*)(g_part + wks * 512 + gr0 * 4);
            gp[0] = r00; gp[1] = r01;
            gp[2] = r10; gp[3] = r11;
        }
        __syncthreads();

        if (tid < 128) {
            float gv[4];
            #pragma unroll
            for (int g = 0; g < 4; g++) {
                float sum = xw[g];
                int gi = (g * 32 + e_u) * 4 + e_b;
                #pragma unroll
                for (int ks = 0; ks < 4; ks++) sum += g_part[ks * 512 + gi];
                gv[g] = sum;
            }
            float c2 = hsig(gv[1]) * c_reg + hsig(gv[0]) * htanh(gv[2]);
            float h2 = hsig(gv[3]) * htanh(c2);
            bool upd = (s < e_len);
            float hn;
            if (upd) { c_reg = c2; hn = h2; }
            else     { hn = h_s[p * 1024 + e_b * 256 + e_gu]; }
            float q0 = hn;
            float q1 = __shfl_sync(0xffffffffu, hn, lane + 4);
            float q2 = __shfl_sync(0xffffffffu, hn, lane + 8);
            float q3 = __shfl_sync(0xffffffffu, hn, lane + 12);
            if ((e_u & 3) == 0) {
                uint32_t off = (uint32_t)((q * 1024 + e_b * 256 + e_gu) * 4);
                uint32_t mst = mbd_st[q];
                #pragma unroll
                for (int i = 0; i < CLUSTER; i++) {
                    int prr = (rot + i) & 7;
                    st_async_v4(peer_base[prr] + off, q0, q1, q2, q3,
                                peer_base[prr] + mst);
                }
            }
        }
        mbar_wait(hs_base + mbd_my[q], ph[q]);
        ph[q] ^= 1;
    }

    __syncthreads();
    {
        int qf = ((t_end - 1) & 1) ^ 1;
        if (tid < 128)
            g_hfinal[dir][bg * 4 + e_b][e_gu] = h_s[qf * 1024 + e_b * 256 + e_gu];
    }

    CLUSTER_SYNC();
}

// ---------------- FC + BN + relu + log_softmax; also resets gemm flags -----
__global__ void final_kernel(const float* __restrict__ fc_w, const float* __restrict__ fc_b,
                             const float* __restrict__ gamma, const float* __restrict__ beta,
                             float* __restrict__ out) {
    __shared__ float wsh[2 * H_];
    __shared__ float lg[B_];
    int j = blockIdx.x;
    int tid = threadIdx.x, warp = tid >> 5, lane = tid & 31;
    if (j == 0 && tid < 2 * MTILES) ((int*)g_xw_flag)[tid] = 0;  // reset for next replay
    for (int i = tid; i < 2 * H_; i += 256) wsh[i] = fc_w[j * 2 * H_ + i];
    __syncthreads();

    #pragma unroll
    for (int ii = 0; ii < 4; ii++) {
        int i = warp * 4 + ii;
        int dirc = i >> 4;
        int bb = (i & 15) * 2;
        const float* h0 = g_hfinal[dirc][bb];
        const float* h1 = g_hfinal[dirc][bb + 1];
        float p = 0.f;
        for (int k = lane; k < H_; k += 32) p += h0[k] * wsh[k] + h1[k] * wsh[H_ + k];
        #pragma unroll
        for (int o = 16; o; o >>= 1) p += __shfl_xor_sync(0xffffffffu, p, o);
        if (lane == 0) lg[i] = p + fc_b[j];
    }
    __syncthreads();

    if (warp == 0) {
        float v = lg[lane];
        float sum = v;
        #pragma unroll
        for (int o = 16; o; o >>= 1) sum += __shfl_xor_sync(0xffffffffu, sum, o);
        float mu = sum * (1.f / 32.f);
        float d = v - mu;
        float vs = d * d;
        #pragma unroll
        for (int o = 16; o; o >>= 1) vs += __shfl_xor_sync(0xffffffffu, vs, o);
        float var = vs * (1.f / 32.f);
        float y = gamma[j] * d * rsqrtf(var + 1e-5f) + beta[j];
        y = fmaxf(y, 0.f);
        float mx = y;
        #pragma unroll
        for (int o = 16; o; o >>= 1) mx = fmaxf(mx, __shfl_xor_sync(0xffffffffu, mx, o));
        float ev = expf(y - mx);
        float se = ev;
        #pragma unroll
        for (int o = 16; o; o >>= 1) se += __shfl_xor_sync(0xffffffffu, se, o);
        out[lane * OUTD + j] = y - mx - logf(se);
    }
}

// ---------------- launch ----------------
extern "C" void kernel_launch(void* const* d_in, const int* in_sizes, int n_in,
                              void* d_out, int out_size) {
    const int*           x      = (const int*)d_in[0];
    const unsigned char* xmask  = (const unsigned char*)d_in[1];
    const float*         xfeat  = (const float*)d_in[2];
    const int*           lens   = (const int*)d_in[3];
    const float* emb    = (const float*)d_in[6];
    const float* attn_w = (const float*)d_in[7];
    const float* attn_b = (const float*)d_in[8];
    const float* wih_f  = (const float*)d_in[9];
    const float* whh_f  = (const float*)d_in[10];
    const float* bih_f  = (const float*)d_in[11];
    const float* bhh_f  = (const float*)d_in[12];
    const float* wih_b  = (const float*)d_in[13];
    const float* whh_b  = (const float*)d_in[14];
    const float* bih_b  = (const float*)d_in[15];
    const float* bhh_b  = (const float*)d_in[16];
    const float* fc_w   = (const float*)d_in[17];
    const float* fc_b   = (const float*)d_in[18];
    const float* bn_g   = (const float*)d_in[19];
    const float* bn_b   = (const float*)d_in[20];

    cudaFuncSetAttribute(xw_gemm_kernel, cudaFuncAttributeMaxDynamicSharedMemorySize,
                         GEMM_SMEM);

    detect_mask_kernel<<<64, 256>>>((const uint4*)xmask, (B_ * S_ * T_) / 16);
    stage1_kernel<<<B_ * S_, 256>>>(x, xmask, xfeat, emb, attn_w, attn_b, lens);
    xw_gemm_kernel<<<dim3(MTILES, GH / 128, 2), 256, GEMM_SMEM>>>(
        wih_f, wih_b, bih_f, bhh_f, bih_b, bhh_b, lens);

    // lstm with programmatic dependent launch: starts while the gemm is
    // still running; per-tile flags gate its XW consumption.
    {
        cudaLaunchConfig_t cfg = {};
        cfg.gridDim = dim3(128, 1, 1);
        cfg.blockDim = dim3(512, 1, 1);
        cfg.dynamicSmemBytes = 0;
        cfg.stream = 0;
        cudaLaunchAttribute at[1];
        at[0].id = cudaLaunchAttributeProgrammaticStreamSerialization;
        at[0].val.programmaticStreamSerializationAllowed = 1;
        cfg.attrs = at;
        cfg.numAttrs = 1;
        cudaLaunchKernelEx(&cfg, lstm_kernel, whh_f, whh_b, lens);
    }

    final_kernel<<<OUTD, 256>>>(fc_w, fc_b, bn_g, bn_b, (float*)d_out);
}